// round 13
// baseline (speedup 1.0000x reference)
#include <cuda_runtime.h>
#include <cuda_bf16.h>
#include <math.h>
#include <stdint.h>

#define BATCH   32
#define CCH     3
#define IMGSZ   224
#define PSZ     16
#define GRIDSZ  14
#define NPATCH  196
#define DIM     768
#define NHEAD   12
#define NLAYER  12
#define DFFN    3072
#define DH      64
#define NCLS    100
#define SELL    3
#define KEEP    137
#define LFULL   197
#define LPRUNE  138
#define LNEPS   1e-6f

typedef __nv_bfloat16 bf16;

// ---------------- weight arena offsets (bf16 [N,K] transposed) --------------
#define OFF_QKV   0ull
#define OFF_PROJ  (OFF_QKV  + 12ull*2304*768)
#define OFF_W1    (OFF_PROJ + 12ull*768*768)
#define OFF_W2    (OFF_W1   + 12ull*3072*768)
#define W_TOTAL   (OFF_W2   + 12ull*768*3072)

// ---------------- scratch (static device globals) ---------------------------
__device__ __align__(16) float g_X  [BATCH*LFULL*DIM];
__device__ __align__(16) float g_X2 [BATCH*LFULL*DIM];
__device__ __align__(16) float g_Hf [BATCH*LFULL*DIM];
__device__ __align__(16) float g_QKV[BATCH*LFULL*3*DIM];
__device__ __align__(16) float g_O  [BATCH*LFULL*DIM];
__device__ __align__(16) float g_M1 [BATCH*LFULL*DFFN];
__device__ __align__(16) float g_PT [BATCH*NPATCH*DIM];
__device__ __align__(16) float g_PE [BATCH*NPATCH*DIM];
__device__ __align__(16) float g_SIM[BATCH*NPATCH];
__device__               int   g_IDX[BATCH*KEEP];
// bf16 split activations (mma path, layers > SELL): hi + mid only
__device__ __align__(16) bf16 g_AH [BATCH*LFULL*DIM];
__device__ __align__(16) bf16 g_AM [BATCH*LFULL*DIM];
__device__ __align__(16) bf16 g_OH [BATCH*LFULL*DIM];
__device__ __align__(16) bf16 g_OM [BATCH*LFULL*DIM];
__device__ __align__(16) bf16 g_M1H[BATCH*LFULL*DFFN];
__device__ __align__(16) bf16 g_M1M[BATCH*LFULL*DFFN];
// bf16 split transposed weights (hi + mid)
__device__ __align__(16) bf16 g_WH[W_TOTAL];
__device__ __align__(16) bf16 g_WM[W_TOTAL];

// ---------------- helpers ----------------------------------------------------
__device__ __forceinline__ uint32_t smem_u32(const void* p){
    uint32_t a;
    asm("{ .reg .u64 t; cvta.to.shared.u64 t, %1; cvt.u32.u64 %0, t; }" : "=r"(a) : "l"(p));
    return a;
}
__device__ __forceinline__ void cpasync16(uint32_t dst, const void* src, int sz){
    asm volatile("cp.async.cg.shared.global [%0], [%1], 16, %2;"
                 :: "r"(dst), "l"(src), "r"(sz));
}
#define CP_COMMIT() asm volatile("cp.async.commit_group;" ::: "memory")
#define CP_WAIT1()  asm volatile("cp.async.wait_group 1;"  ::: "memory")

#define LDSM4(r0,r1,r2,r3,addr) \
    asm volatile("ldmatrix.sync.aligned.m8n8.x4.shared.b16 {%0,%1,%2,%3}, [%4];" \
        : "=r"(r0),"=r"(r1),"=r"(r2),"=r"(r3) : "r"(addr))

#define MMA16816(d, a, b) \
    asm volatile("mma.sync.aligned.m16n8k16.row.col.f32.bf16.bf16.f32 " \
        "{%0,%1,%2,%3}, {%4,%5,%6,%7}, {%8,%9}, {%0,%1,%2,%3};" \
        : "+f"((d)[0]),"+f"((d)[1]),"+f"((d)[2]),"+f"((d)[3]) \
        : "r"((a)[0]),"r"((a)[1]),"r"((a)[2]),"r"((a)[3]), "r"((b)[0]),"r"((b)[1]))

__device__ __forceinline__ void split2(float x, bf16& h, bf16& m)
{
    h = __float2bfloat16(x);
    float r = x - __bfloat162float(h);
    m = __float2bfloat16(r);
}

// ---------------- weight transpose + split2: W[K,N] fp32 -> [N,K] bf16 x2 ---
__global__ void wsplit_kernel(const float* __restrict__ W, bf16* __restrict__ Oh,
                              bf16* __restrict__ Om, int K, int N)
{
    __shared__ float t[32][33];
    int k0 = blockIdx.x * 32, n0 = blockIdx.y * 32;
    int tx = threadIdx.x, ty = threadIdx.y;      // (32, 8)
    const float* Wp = W + (size_t)blockIdx.z * K * N;
    size_t ob = (size_t)blockIdx.z * N * K;
    #pragma unroll
    for (int r = ty; r < 32; r += 8)
        t[r][tx] = Wp[(size_t)(k0 + r) * N + n0 + tx];
    __syncthreads();
    #pragma unroll
    for (int r = ty; r < 32; r += 8) {
        float x = t[tx][r];
        bf16 h, m; split2(x, h, m);
        size_t o = ob + (size_t)(n0 + r) * K + k0 + tx;
        Oh[o] = h; Om[o] = m;
    }
}

// ---------------- im2col (fp32) ---------------------------------------------
__global__ void im2col_kernel(const float* __restrict__ inp, float* __restrict__ PT)
{
    size_t idx = (size_t)blockIdx.x * 256 + threadIdx.x;
    const size_t total = (size_t)BATCH * NPATCH * DIM;
    if (idx >= total) return;
    int k = (int)(idx % DIM);
    int p = (int)((idx / DIM) % NPATCH);
    int b = (int)(idx / ((size_t)DIM * NPATCH));
    int c  = k / (PSZ*PSZ);
    int py = (k / PSZ) % PSZ;
    int px = k % PSZ;
    int gy = p / GRIDSZ, gx = p % GRIDSZ;
    PT[idx] = inp[(((size_t)b*CCH + c)*IMGSZ + (size_t)gy*PSZ + py)*IMGSZ + gx*PSZ + px];
}

// ---------------- FFMA2 SGEMM (fp32 path) -----------------------------------
// BIT-EXACT k-ascending fma.rn.f32x2 chain per element; frozen epilogue order.
// Block tile 128(m) x 256(n), microtile 8x16, K-tile 16. A staged non-dup,
// register-dup; B 64B/thread/kk -> 0.75 B/MAC (FMA2-issue-bound, not LDS).
// mode 0: plain; 1: +residual; 2: tanh-GELU
#define SMEM_F32 49152   // As [2][16][128] 16KB + Bs [2][16][256] 32KB

__global__ void __launch_bounds__(256, 1)
gemm128_kernel(const float* __restrict__ A, const float* __restrict__ Bm,
               const float* __restrict__ bias, const float* __restrict__ res,
               float* __restrict__ C, int M, int N, int K, int mode)
{
    extern __shared__ float smf[];
    float* As = smf;                  // [2][16][128]
    float* Bs = smf + 2*16*128;       // [2][16][256]
    int tid = threadIdx.x;
    int tx = tid & 15, ty = tid >> 4;
    int m0 = blockIdx.y * 128, n0 = blockIdx.x * 256;
    int ar = tid >> 1, ak8 = (tid & 1) * 8;   // A: row, k-offset (8 floats)
    bool avalid = (m0 + ar) < M;
    const float* Aptr = A + (size_t)(m0 + ar) * K + ak8;
    const float4 z4 = make_float4(0.f,0.f,0.f,0.f);
    int T = K >> 4;

    // B loader mapping: 4 quads/thread; q = tid + 256*i -> kr = q>>6, c4 = q&63
    int kr[4], c4[4]; bool bval[4];
    #pragma unroll
    for (int i = 0; i < 4; i++) {
        int q = tid + 256*i;
        kr[i] = q >> 6; c4[i] = q & 63;
        bval[i] = (n0 + c4[i]*4) < N;
    }

    float4 av0 = avalid ? *(const float4*)Aptr        : z4;
    float4 av1 = avalid ? *(const float4*)(Aptr + 4)  : z4;
    float4 bq[4];
    #pragma unroll
    for (int i = 0; i < 4; i++)
        bq[i] = bval[i] ? *(const float4*)(Bm + (size_t)kr[i]*N + n0 + c4[i]*4) : z4;
    {
        float va[8] = {av0.x,av0.y,av0.z,av0.w,av1.x,av1.y,av1.z,av1.w};
        #pragma unroll
        for (int q = 0; q < 8; q++)
            As[(0*16 + ak8 + q)*128 + ar] = va[q];
        #pragma unroll
        for (int i = 0; i < 4; i++)
            *(float4*)&Bs[(0*16 + kr[i])*256 + c4[i]*4] = bq[i];
    }
    __syncthreads();

    unsigned long long acc2[8][8];
    #pragma unroll
    for (int i = 0; i < 8; i++)
        #pragma unroll
        for (int j = 0; j < 8; j++) acc2[i][j] = 0ull;

    for (int t = 0; t < T; t++) {
        int cur = t & 1;
        if (t + 1 < T) {
            const float* Ap = Aptr + (size_t)(t+1)*16;
            av0 = avalid ? *(const float4*)Ap       : z4;
            av1 = avalid ? *(const float4*)(Ap + 4) : z4;
            #pragma unroll
            for (int i = 0; i < 4; i++)
                bq[i] = bval[i] ? *(const float4*)(Bm + (size_t)((t+1)*16 + kr[i])*N + n0 + c4[i]*4) : z4;
        }
        #pragma unroll
        for (int kk = 0; kk < 16; kk++) {
            const float* ap = &As[(cur*16 + kk)*128 + ty*8];
            float4 a0 = *(const float4*)ap;
            float4 a1 = *(const float4*)(ap + 4);
            float af[8] = {a0.x,a0.y,a0.z,a0.w,a1.x,a1.y,a1.z,a1.w};
            unsigned long long a2[8];
            #pragma unroll
            for (int i = 0; i < 8; i++)
                asm("mov.b64 %0, {%1, %1};" : "=l"(a2[i]) : "f"(af[i]));
            const ulonglong2* pb = (const ulonglong2*)&Bs[(cur*16 + kk)*256 + tx*16];
            ulonglong2 q0 = pb[0], q1 = pb[1], q2 = pb[2], q3 = pb[3];
            unsigned long long b2[8] = {q0.x,q0.y,q1.x,q1.y,q2.x,q2.y,q3.x,q3.y};
            #pragma unroll
            for (int i = 0; i < 8; i++)
                #pragma unroll
                for (int j = 0; j < 8; j++)
                    asm("fma.rn.f32x2 %0, %1, %2, %0;"
                        : "+l"(acc2[i][j]) : "l"(a2[i]), "l"(b2[j]));
        }
        if (t + 1 < T) {
            int nxt = cur ^ 1;
            float va[8] = {av0.x,av0.y,av0.z,av0.w,av1.x,av1.y,av1.z,av1.w};
            #pragma unroll
            for (int q = 0; q < 8; q++)
                As[(nxt*16 + ak8 + q)*128 + ar] = va[q];
            #pragma unroll
            for (int i = 0; i < 4; i++)
                *(float4*)&Bs[(nxt*16 + kr[i])*256 + c4[i]*4] = bq[i];
            __syncthreads();
        }
    }
    #pragma unroll
    for (int i = 0; i < 8; i++) {
        int m = m0 + ty*8 + i;
        if (m >= M) continue;
        float c[16];
        #pragma unroll
        for (int j = 0; j < 8; j++)
            asm("mov.b64 {%0, %1}, %2;" : "=f"(c[2*j]), "=f"(c[2*j+1]) : "l"(acc2[i][j]));
        #pragma unroll
        for (int j = 0; j < 16; j++) {
            int n = n0 + tx*16 + j;
            if (n >= N) continue;
            float v = c[j] + bias[n];
            if (mode == 1) {
                v += res[(size_t)m*N + n];
            } else if (mode == 2) {
                float x = v;
                v = 0.5f * x * (1.0f + tanhf(0.7978845608028654f * (x + 0.044715f*x*x*x)));
            }
            C[(size_t)m*N + n] = v;
        }
    }
}

// ---------------- mma.sync bf16 2-split/3-product GEMM (layers > SELL) ------
#define APITCH   144
#define SPLIT_SZ (128*APITCH)          // 18432
#define STG_SZ   (4*SPLIT_SZ)          // 73728
#define SMEM_MMA (2*STG_SZ)            // 147456

__global__ void __launch_bounds__(512, 1)
gemm_mma(const bf16* __restrict__ Ah, const bf16* __restrict__ Am,
         const bf16* __restrict__ Bh, const bf16* __restrict__ Bm,
         const float* __restrict__ bias, const float* __restrict__ res,
         float* __restrict__ Cf, bf16* __restrict__ Ch, bf16* __restrict__ Cm,
         int M, int N, int K, int mode)
{
    extern __shared__ char smem[];
    uint32_t sb = smem_u32(smem);
    int tid = threadIdx.x, lane = tid & 31, warp = tid >> 5;
    int wm = warp >> 2, wn = warp & 3;         // 4 x 4 warps, 32x32 tile each
    int m0 = blockIdx.y * 128, n0 = blockIdx.x * 128;

    float acc[2][4][4] = {};
    int lr = lane & 15;
    int lk = (lane >> 4) * 16;
    int T = K >> 6;                            // K/64 tiles

    auto issue_stage = [&](int buf, int kc) {
        uint32_t base = sb + buf * STG_SZ;
        #pragma unroll
        for (int j = 0; j < 2; j++) {
            int u = j * 512 + tid;
            int row = u >> 3, q = u & 7;       // 128 rows x 8 quads(16B)
            uint32_t d = base + row*APITCH + q*16;
            size_t goff = (size_t)row * K + kc + q*8;
            int asz = (m0 + row < M) ? 16 : 0;
            cpasync16(d + 0*SPLIT_SZ, Ah + (size_t)m0*K + goff, asz);
            cpasync16(d + 1*SPLIT_SZ, Am + (size_t)m0*K + goff, asz);
            cpasync16(d + 2*SPLIT_SZ, Bh + (size_t)n0*K + goff, 16);
            cpasync16(d + 3*SPLIT_SZ, Bm + (size_t)n0*K + goff, 16);
        }
    };

    issue_stage(0, 0);
    CP_COMMIT();

    for (int t = 0; t < T; t++) {
        if (t + 1 < T) issue_stage((t + 1) & 1, (t + 1) * 64);
        CP_COMMIT();
        CP_WAIT1();
        __syncthreads();

        uint32_t stg = sb + (t & 1) * STG_SZ;
        #pragma unroll
        for (int kh = 0; kh < 4; kh++) {
            int kb = kh * 32 + lk;
            uint32_t afr[2][2][4], bfr[2][4][2];
            #pragma unroll
            for (int s = 0; s < 2; s++) {
                #pragma unroll
                for (int mt = 0; mt < 2; mt++) {
                    uint32_t ad = stg + s*SPLIT_SZ + (uint32_t)(wm*32 + mt*16 + lr)*APITCH + kb;
                    LDSM4(afr[s][mt][0], afr[s][mt][1], afr[s][mt][2], afr[s][mt][3], ad);
                }
                #pragma unroll
                for (int np = 0; np < 2; np++) {
                    uint32_t r0, r1, r2, r3;
                    uint32_t bd = stg + (2+s)*SPLIT_SZ + (uint32_t)(wn*32 + np*16 + lr)*APITCH + kb;
                    LDSM4(r0, r1, r2, r3, bd);
                    bfr[s][np*2+0][0] = r0; bfr[s][np*2+0][1] = r2;
                    bfr[s][np*2+1][0] = r1; bfr[s][np*2+1][1] = r3;
                }
            }
            // products: hh, hm, mh
            #pragma unroll
            for (int p = 0; p < 3; p++) {
                int sa = (p == 2) ? 1 : 0;
                int sbp = (p == 1) ? 1 : 0;
                #pragma unroll
                for (int mt = 0; mt < 2; mt++)
                    #pragma unroll
                    for (int nt = 0; nt < 4; nt++)
                        MMA16816(acc[mt][nt], afr[sa][mt], bfr[sbp][nt]);
            }
        }
        __syncthreads();
    }

    // ---- epilogue
    #pragma unroll
    for (int mt = 0; mt < 2; mt++) {
        #pragma unroll
        for (int h2 = 0; h2 < 2; h2++) {
            int rr = m0 + wm*32 + mt*16 + (lane >> 2) + h2*8;
            if (rr >= M) continue;
            #pragma unroll
            for (int nt = 0; nt < 4; nt++) {
                int c = n0 + wn*32 + nt*8 + (lane & 3)*2;
                float v0 = acc[mt][nt][h2*2+0] + bias[c];
                float v1 = acc[mt][nt][h2*2+1] + bias[c+1];
                size_t o = (size_t)rr * N + c;
                if (mode == 1) { v0 += res[o]; v1 += res[o+1]; }
                if (mode <= 1) {
                    float2 v; v.x = v0; v.y = v1;
                    *(float2*)&Cf[o] = v;
                } else {
                    float g0 = 0.5f*v0*(1.0f + tanhf(0.7978845608028654f*(v0 + 0.044715f*v0*v0*v0)));
                    float g1 = 0.5f*v1*(1.0f + tanhf(0.7978845608028654f*(v1 + 0.044715f*v1*v1*v1)));
                    bf16 h0, m0b, h1, m1b;
                    split2(g0, h0, m0b);
                    split2(g1, h1, m1b);
                    *(__nv_bfloat162*)&Ch[o] = __nv_bfloat162(h0, h1);
                    *(__nv_bfloat162*)&Cm[o] = __nv_bfloat162(m0b, m1b);
                }
            }
        }
    }
}

// ---------------- layernorm: fp32 out and/or split2 out ---------------------
__global__ void ln_kernel(const float* __restrict__ X, const float* __restrict__ g,
                          const float* __restrict__ b, float* __restrict__ Yf,
                          bf16* __restrict__ Yh, bf16* __restrict__ Ym)
{
    int row = blockIdx.x;
    const float* x = X + (size_t)row * DIM;
    __shared__ float red[256];
    int tid = threadIdx.x;
    float v0 = x[tid], v1 = x[tid+256], v2 = x[tid+512];
    red[tid] = v0 + v1 + v2;
    __syncthreads();
    for (int o = 128; o > 0; o >>= 1) { if (tid < o) red[tid] += red[tid+o]; __syncthreads(); }
    float mean = red[0] * (1.0f / DIM);
    __syncthreads();
    float d0 = v0-mean, d1 = v1-mean, d2 = v2-mean;
    red[tid] = d0*d0 + d1*d1 + d2*d2;
    __syncthreads();
    for (int o = 128; o > 0; o >>= 1) { if (tid < o) red[tid] += red[tid+o]; __syncthreads(); }
    float rstd = 1.0f / sqrtf(red[0] * (1.0f / DIM) + LNEPS);
    size_t base = (size_t)row * DIM;
    float o0 = d0*rstd*g[tid]     + b[tid];
    float o1 = d1*rstd*g[tid+256] + b[tid+256];
    float o2 = d2*rstd*g[tid+512] + b[tid+512];
    if (Yf) { Yf[base+tid] = o0; Yf[base+tid+256] = o1; Yf[base+tid+512] = o2; }
    if (Yh) {
        bf16 h, m;
        split2(o0, h, m); Yh[base+tid]     = h; Ym[base+tid]     = m;
        split2(o1, h, m); Yh[base+tid+256] = h; Ym[base+tid+256] = m;
        split2(o2, h, m); Yh[base+tid+512] = h; Ym[base+tid+512] = m;
    }
}

// ---------------- assemble X = [cls | patches] + pos ------------------------
__global__ void assemble_kernel(const float* __restrict__ PE, const float* __restrict__ cls,
                                const float* __restrict__ pos, float* __restrict__ X)
{
    size_t idx = (size_t)blockIdx.x * 256 + threadIdx.x;
    const size_t total = (size_t)BATCH * LFULL * DIM;
    if (idx >= total) return;
    int d = (int)(idx % DIM);
    int r = (int)((idx / DIM) % LFULL);
    int b = (int)(idx / ((size_t)LFULL * DIM));
    float v = (r == 0) ? cls[d] : PE[((size_t)b*NPATCH + (r-1))*DIM + d];
    X[idx] = v + pos[(size_t)r*DIM + d];
}

// ---------------- tiled attention v3: register microtiles, LDS-lean ---------
#define QT 32
#define KC 32
__global__ void __launch_bounds__(256)
attn3_kernel(const float* __restrict__ QKV, float* __restrict__ Of,
             bf16* __restrict__ Oh, bf16* __restrict__ Om, int L)
{
    int q0b = blockIdx.x * QT;
    int h  = blockIdx.y;
    int b  = blockIdx.z;
    __shared__ float Qt[DH][34];                 // Q transposed [d][q]
    __shared__ __align__(16) float KVu[64*36];   // union: Kt[d][kk] pitch 36 / Vs[kk][d] pitch 68
    __shared__ float sc[QT][224];
    int tid = threadIdx.x;
    const size_t rs = 3 * DIM;
    const float* base = QKV + (size_t)b * L * rs;

    // load Q transposed
    for (int i = tid; i < QT*DH; i += 256) {
        int qq = i >> 6, d = i & 63;
        Qt[d][qq] = (q0b + qq < L) ? base[(size_t)(q0b+qq)*rs + h*DH + d] : 0.f;
    }

    int ty = tid >> 4, tx = tid & 15;            // score: 2q x 2k ; V: 2q x 4d
    // ---- score pass
    for (int kc = 0; kc < L; kc += KC) {
        __syncthreads();
        for (int i = tid; i < KC*DH; i += 256) {
            int kk = i >> 6, d = i & 63;
            KVu[d*36 + kk] = (kc + kk < L) ? base[(size_t)(kc+kk)*rs + DIM + h*DH + d] : 0.f;
        }
        __syncthreads();
        float a00 = 0.f, a01 = 0.f, a10 = 0.f, a11 = 0.f;
        #pragma unroll 8
        for (int d = 0; d < DH; d++) {
            float2 qv = *(const float2*)&Qt[d][2*ty];
            float k0 = KVu[d*36 + 2*tx];
            float k1 = KVu[d*36 + 2*tx + 1];
            a00 += qv.x * k0; a01 += qv.x * k1;
            a10 += qv.y * k0; a11 += qv.y * k1;
        }
        int k0i = kc + 2*tx, k1i = k0i + 1;
        sc[2*ty+0][k0i] = (k0i < L) ? a00 * 0.125f : -1e30f;
        sc[2*ty+0][k1i] = (k1i < L) ? a01 * 0.125f : -1e30f;
        sc[2*ty+1][k0i] = (k0i < L) ? a10 * 0.125f : -1e30f;
        sc[2*ty+1][k1i] = (k1i < L) ? a11 * 0.125f : -1e30f;
    }
    __syncthreads();
    // ---- softmax (identical code to previous rounds)
    int wid = tid >> 5, lane = tid & 31;
    for (int qq = wid; qq < QT; qq += 8) {
        float mx = -1e30f;
        for (int k = lane; k < L; k += 32) mx = fmaxf(mx, sc[qq][k]);
        for (int o = 16; o; o >>= 1) mx = fmaxf(mx, __shfl_xor_sync(~0u, mx, o));
        float sum = 0.f;
        for (int k = lane; k < L; k += 32) { float e = expf(sc[qq][k] - mx); sc[qq][k] = e; sum += e; }
        for (int o = 16; o; o >>= 1) sum += __shfl_xor_sync(~0u, sum, o);
        float inv = 1.0f / sum;
        for (int k = lane; k < L; k += 32) sc[qq][k] *= inv;
    }
    // ---- V pass: thread owns rows (2*ty, 2*ty+1) x cols (4*tx .. 4*tx+3)
    float ov0[4] = {}, ov1[4] = {};
    int d0 = 4 * tx;
    for (int kc = 0; kc < L; kc += KC) {
        __syncthreads();
        for (int i = tid; i < KC*DH; i += 256) {
            int kk = i >> 6, dd = i & 63;
            KVu[kk*68 + dd] = (kc + kk < L) ? base[(size_t)(kc+kk)*rs + 2*DIM + h*DH + dd] : 0.f;
        }
        __syncthreads();
        int kmax = min(KC, L - kc);
        for (int kk = 0; kk < kmax; kk++) {
            float s0 = sc[2*ty+0][kc+kk];
            float s1 = sc[2*ty+1][kc+kk];
            float4 v = *(const float4*)&KVu[kk*68 + d0];
            ov0[0] += s0 * v.x; ov0[1] += s0 * v.y; ov0[2] += s0 * v.z; ov0[3] += s0 * v.w;
            ov1[0] += s1 * v.x; ov1[1] += s1 * v.y; ov1[2] += s1 * v.z; ov1[3] += s1 * v.w;
        }
    }
    #pragma unroll
    for (int i = 0; i < 2; i++) {
        int q = q0b + 2*ty + i;
        if (q >= L) continue;
        const float* src = (i == 0) ? ov0 : ov1;
        size_t o = ((size_t)(b*L + q))*DIM + h*DH + d0;
        if (Of) {
            *(float4*)&Of[o] = make_float4(src[0], src[1], src[2], src[3]);
        } else {
            bf16 h0, m0v, h1, m1v;
            #pragma unroll
            for (int j = 0; j < 4; j += 2) {
                split2(src[j],   h0, m0v);
                split2(src[j+1], h1, m1v);
                *(__nv_bfloat162*)&Oh[o + j] = __nv_bfloat162(h0, h1);
                *(__nv_bfloat162*)&Om[o + j] = __nv_bfloat162(m0v, m1v);
            }
        }
    }
}

// ---------------- cosine similarity (fp64) ----------------------------------
__global__ void sim_kernel(const float* __restrict__ X, float* __restrict__ SIM)
{
    int p = blockIdx.x, b = blockIdx.y;
    const float* cls = X + (size_t)b * LFULL * DIM;
    const float* pt  = X + ((size_t)b*LFULL + 1 + p) * DIM;
    int tid = threadIdx.x;
    double dot = 0.0, nc = 0.0, np = 0.0;
    for (int d = tid; d < DIM; d += 128) {
        double c = (double)cls[d], v = (double)pt[d];
        dot += c*v; nc += c*c; np += v*v;
    }
    __shared__ double r1[128], r2[128], r3[128];
    r1[tid] = dot; r2[tid] = nc; r3[tid] = np;
    __syncthreads();
    for (int o = 64; o > 0; o >>= 1) {
        if (tid < o) { r1[tid]+=r1[tid+o]; r2[tid]+=r2[tid+o]; r3[tid]+=r3[tid+o]; }
        __syncthreads();
    }
    if (tid == 0) {
        double den = sqrt(r2[0]) * sqrt(r3[0]);
        den = den > 1e-8 ? den : 1e-8;
        SIM[b*NPATCH + p] = (float)(r1[0] / den);
    }
}

// ---------------- stable top-K ----------------------------------------------
__global__ void topk_kernel(const float* __restrict__ SIM, int* __restrict__ IDX)
{
    int b = blockIdx.x;
    __shared__ float s[NPATCH];
    int tid = threadIdx.x;
    if (tid < NPATCH) s[tid] = SIM[b*NPATCH + tid];
    __syncthreads();
    if (tid < NPATCH) {
        float si = s[tid];
        int rank = 0;
        for (int j = 0; j < NPATCH; j++) {
            float sj = s[j];
            rank += (sj > si) || (sj == si && j < tid);
        }
        if (rank < KEEP) IDX[b*KEEP + rank] = tid;
    }
}

// ---------------- gather ----------------------------------------------------
__global__ void gather_kernel(const float* __restrict__ X, const int* __restrict__ IDX,
                              float* __restrict__ X2)
{
    size_t idx = (size_t)blockIdx.x * 256 + threadIdx.x;
    const size_t total = (size_t)BATCH * LPRUNE * DIM;
    if (idx >= total) return;
    int d = (int)(idx % DIM);
    int r = (int)((idx / DIM) % LPRUNE);
    int b = (int)(idx / ((size_t)LPRUNE * DIM));
    int src = (r == 0) ? 0 : (1 + IDX[b*KEEP + (r-1)]);
    X2[idx] = X[((size_t)b*LFULL + src)*DIM + d];
}

// ---------------- host orchestration ----------------------------------------
extern "C" void kernel_launch(void* const* d_in, const int* in_sizes, int n_in,
                              void* d_out, int out_size)
{
    const float* inputs    = (const float*)d_in[0];
    const float* patch_w   = (const float*)d_in[1];
    const float* patch_b   = (const float*)d_in[2];
    const float* cls_token = (const float*)d_in[3];
    const float* pos_embed = (const float*)d_in[4];
    const float* qkv_w     = (const float*)d_in[5];
    const float* qkv_b     = (const float*)d_in[6];
    const float* proj_w    = (const float*)d_in[7];
    const float* proj_b    = (const float*)d_in[8];
    const float* ln1_g     = (const float*)d_in[9];
    const float* ln1_b     = (const float*)d_in[10];
    const float* ln2_g     = (const float*)d_in[11];
    const float* ln2_b     = (const float*)d_in[12];
    const float* mlp_w1    = (const float*)d_in[13];
    const float* mlp_b1    = (const float*)d_in[14];
    const float* mlp_w2    = (const float*)d_in[15];
    const float* mlp_b2    = (const float*)d_in[16];
    const float* norm_g    = (const float*)d_in[17];
    const float* norm_b    = (const float*)d_in[18];
    const float* head_w    = (const float*)d_in[19];
    const float* head_b    = (const float*)d_in[20];

    float *X, *X2, *Hf, *QKV, *Ofp, *M1f, *PT, *PE, *SIM; int* IDX;
    bf16 *AH, *AM, *OH, *OM, *M1H, *M1M, *WH, *WM;
    cudaGetSymbolAddress((void**)&X,   g_X);
    cudaGetSymbolAddress((void**)&X2,  g_X2);
    cudaGetSymbolAddress((void**)&Hf,  g_Hf);
    cudaGetSymbolAddress((void**)&QKV, g_QKV);
    cudaGetSymbolAddress((void**)&Ofp, g_O);
    cudaGetSymbolAddress((void**)&M1f, g_M1);
    cudaGetSymbolAddress((void**)&PT,  g_PT);
    cudaGetSymbolAddress((void**)&PE,  g_PE);
    cudaGetSymbolAddress((void**)&SIM, g_SIM);
    cudaGetSymbolAddress((void**)&IDX, g_IDX);
    cudaGetSymbolAddress((void**)&AH,  g_AH);  cudaGetSymbolAddress((void**)&AM, g_AM);
    cudaGetSymbolAddress((void**)&OH,  g_OH);  cudaGetSymbolAddress((void**)&OM, g_OM);
    cudaGetSymbolAddress((void**)&M1H, g_M1H); cudaGetSymbolAddress((void**)&M1M, g_M1M);
    cudaGetSymbolAddress((void**)&WH,  g_WH);  cudaGetSymbolAddress((void**)&WM, g_WM);

    cudaFuncSetAttribute(gemm_mma, cudaFuncAttributeMaxDynamicSharedMemorySize, SMEM_MMA);
    cudaFuncSetAttribute(gemm128_kernel, cudaFuncAttributeMaxDynamicSharedMemorySize, SMEM_F32);

    // ---- weight prep for mma layers (transpose + split2)
    {
        dim3 blk(32, 8);
        wsplit_kernel<<<dim3(24, 72, 12), blk>>>(qkv_w,  WH+OFF_QKV,  WM+OFF_QKV,  768, 2304);
        wsplit_kernel<<<dim3(24, 24, 12), blk>>>(proj_w, WH+OFF_PROJ, WM+OFF_PROJ, 768, 768);
        wsplit_kernel<<<dim3(24, 96, 12), blk>>>(mlp_w1, WH+OFF_W1,   WM+OFF_W1,   768, 3072);
        wsplit_kernel<<<dim3(96, 24, 12), blk>>>(mlp_w2, WH+OFF_W2,   WM+OFF_W2,   3072, 768);
    }

    // ---- patch embedding (fp32 FFMA2 path — bit-exact chain)
    {
        size_t total = (size_t)BATCH * NPATCH * DIM;
        im2col_kernel<<<(unsigned)((total + 255)/256), 256>>>(inputs, PT);
        dim3 g(3, 49);
        gemm128_kernel<<<g, 256, SMEM_F32>>>(PT, patch_w, patch_b, nullptr, PE,
                                             BATCH*NPATCH, DIM, DIM, 0);
        size_t tot2 = (size_t)BATCH * LFULL * DIM;
        assemble_kernel<<<(unsigned)((tot2 + 255)/256), 256>>>(PE, cls_token, pos_embed, X);
    }

    float* cur = X;
    int L = LFULL;
    for (int n = 0; n < NLAYER; n++) {
        int M = BATCH * L;
        int Mt = (M + 127) / 128;
        if (n <= SELL) {
            // ======== fp32 FFMA2 path (bit-exact frozen numerics; selection-safe)
            ln_kernel<<<M, 256>>>(cur, ln1_g + (size_t)n*DIM, ln1_b + (size_t)n*DIM,
                                  Hf, nullptr, nullptr);
            gemm128_kernel<<<dim3(9, Mt), 256, SMEM_F32>>>(Hf, qkv_w + (size_t)n*DIM*3*DIM,
                qkv_b + (size_t)n*3*DIM, nullptr, QKV, M, 3*DIM, DIM, 0);
            {
                dim3 g((L + QT - 1)/QT, NHEAD, BATCH);
                attn3_kernel<<<g, 256>>>(QKV, Ofp, nullptr, nullptr, L);
            }
            gemm128_kernel<<<dim3(3, Mt), 256, SMEM_F32>>>(Ofp, proj_w + (size_t)n*DIM*DIM,
                proj_b + (size_t)n*DIM, cur, cur, M, DIM, DIM, 1);
            ln_kernel<<<M, 256>>>(cur, ln2_g + (size_t)n*DIM, ln2_b + (size_t)n*DIM,
                                  Hf, nullptr, nullptr);
            gemm128_kernel<<<dim3(12, Mt), 256, SMEM_F32>>>(Hf, mlp_w1 + (size_t)n*DIM*DFFN,
                mlp_b1 + (size_t)n*DFFN, nullptr, M1f, M, DFFN, DIM, 2);
            gemm128_kernel<<<dim3(3, Mt), 256, SMEM_F32>>>(M1f, mlp_w2 + (size_t)n*DFFN*DIM,
                mlp_b2 + (size_t)n*DIM, cur, cur, M, DIM, DFFN, 1);
            if (n == SELL) {
                dim3 gs(NPATCH, BATCH);
                sim_kernel<<<gs, 128>>>(cur, SIM);
                topk_kernel<<<BATCH, 256>>>(SIM, IDX);
                size_t tot = (size_t)BATCH * LPRUNE * DIM;
                gather_kernel<<<(unsigned)((tot + 255)/256), 256>>>(cur, IDX, X2);
                cur = X2;
                L = LPRUNE;
            }
        } else {
            // ======== bf16 mma path (post-selection)
            ln_kernel<<<M, 256>>>(cur, ln1_g + (size_t)n*DIM, ln1_b + (size_t)n*DIM,
                                  nullptr, AH, AM);
            gemm_mma<<<dim3(18, Mt), 512, SMEM_MMA>>>(AH, AM,
                WH+OFF_QKV + (size_t)n*2304*768, WM+OFF_QKV + (size_t)n*2304*768,
                qkv_b + (size_t)n*3*DIM, nullptr, QKV, nullptr, nullptr, M, 3*DIM, DIM, 0);
            {
                dim3 g((L + QT - 1)/QT, NHEAD, BATCH);
                attn3_kernel<<<g, 256>>>(QKV, nullptr, OH, OM, L);
            }
            gemm_mma<<<dim3(6, Mt), 512, SMEM_MMA>>>(OH, OM,
                WH+OFF_PROJ + (size_t)n*768*768, WM+OFF_PROJ + (size_t)n*768*768,
                proj_b + (size_t)n*DIM, cur, cur, nullptr, nullptr, M, DIM, DIM, 1);
            ln_kernel<<<M, 256>>>(cur, ln2_g + (size_t)n*DIM, ln2_b + (size_t)n*DIM,
                                  nullptr, AH, AM);
            gemm_mma<<<dim3(24, Mt), 512, SMEM_MMA>>>(AH, AM,
                WH+OFF_W1 + (size_t)n*3072*768, WM+OFF_W1 + (size_t)n*3072*768,
                mlp_b1 + (size_t)n*DFFN, nullptr, nullptr, M1H, M1M, M, DFFN, DIM, 2);
            gemm_mma<<<dim3(6, Mt), 512, SMEM_MMA>>>(M1H, M1M,
                WH+OFF_W2 + (size_t)n*768*3072, WM+OFF_W2 + (size_t)n*768*3072,
                mlp_b2 + (size_t)n*DIM, cur, cur, nullptr, nullptr, M, DIM, DFFN, 1);
        }
    }

    // ---- final LN + head (fp32 FFMA2 path)
    {
        int M = BATCH * LPRUNE;
        ln_kernel<<<M, 256>>>(cur, norm_g, norm_b, Hf, nullptr, nullptr);
        dim3 g(1, (M + 127)/128);
        gemm128_kernel<<<g, 256, SMEM_F32>>>(Hf, head_w, head_b, nullptr, (float*)d_out,
                                             M, NCLS, DIM, 0);
    }
}

// round 14
// speedup vs baseline: 1.1925x; 1.1925x over previous
#include <cuda_runtime.h>
#include <cuda_bf16.h>
#include <math.h>
#include <stdint.h>

#define BATCH   32
#define CCH     3
#define IMGSZ   224
#define PSZ     16
#define GRIDSZ  14
#define NPATCH  196
#define DIM     768
#define NHEAD   12
#define NLAYER  12
#define DFFN    3072
#define DH      64
#define NCLS    100
#define SELL    3
#define KEEP    137
#define LFULL   197
#define LPRUNE  138
#define LNEPS   1e-6f

typedef __nv_bfloat16 bf16;

// ---------------- weight arena offsets (bf16 [N,K] transposed) --------------
#define OFF_QKV   0ull
#define OFF_PROJ  (OFF_QKV  + 12ull*2304*768)
#define OFF_W1    (OFF_PROJ + 12ull*768*768)
#define OFF_W2    (OFF_W1   + 12ull*3072*768)
#define W_TOTAL   (OFF_W2   + 12ull*768*3072)

// ---------------- scratch (static device globals) ---------------------------
__device__ __align__(16) float g_X  [BATCH*LFULL*DIM];
__device__ __align__(16) float g_X2 [BATCH*LFULL*DIM];
__device__ __align__(16) float g_Hf [BATCH*LFULL*DIM];
__device__ __align__(16) float g_QKV[BATCH*LFULL*3*DIM];
__device__ __align__(16) float g_O  [BATCH*LFULL*DIM];
__device__ __align__(16) float g_M1 [BATCH*LFULL*DFFN];
__device__ __align__(16) float g_PT [BATCH*NPATCH*DIM];
__device__ __align__(16) float g_PE [BATCH*NPATCH*DIM];
__device__ __align__(16) float g_SIM[BATCH*NPATCH];
__device__               int   g_IDX[BATCH*KEEP];
// bf16 split activations (mma path, layers > SELL): hi + mid only
__device__ __align__(16) bf16 g_AH [BATCH*LFULL*DIM];
__device__ __align__(16) bf16 g_AM [BATCH*LFULL*DIM];
__device__ __align__(16) bf16 g_OH [BATCH*LFULL*DIM];
__device__ __align__(16) bf16 g_OM [BATCH*LFULL*DIM];
__device__ __align__(16) bf16 g_M1H[BATCH*LFULL*DFFN];
__device__ __align__(16) bf16 g_M1M[BATCH*LFULL*DFFN];
// bf16 split transposed weights (hi + mid)
__device__ __align__(16) bf16 g_WH[W_TOTAL];
__device__ __align__(16) bf16 g_WM[W_TOTAL];

// ---------------- helpers ----------------------------------------------------
__device__ __forceinline__ uint32_t smem_u32(const void* p){
    uint32_t a;
    asm("{ .reg .u64 t; cvta.to.shared.u64 t, %1; cvt.u32.u64 %0, t; }" : "=r"(a) : "l"(p));
    return a;
}
__device__ __forceinline__ void cpasync16(uint32_t dst, const void* src, int sz){
    asm volatile("cp.async.cg.shared.global [%0], [%1], 16, %2;"
                 :: "r"(dst), "l"(src), "r"(sz));
}
#define CP_COMMIT() asm volatile("cp.async.commit_group;" ::: "memory")
#define CP_WAIT1()  asm volatile("cp.async.wait_group 1;"  ::: "memory")

#define LDSM4(r0,r1,r2,r3,addr) \
    asm volatile("ldmatrix.sync.aligned.m8n8.x4.shared.b16 {%0,%1,%2,%3}, [%4];" \
        : "=r"(r0),"=r"(r1),"=r"(r2),"=r"(r3) : "r"(addr))

#define MMA16816(d, a, b) \
    asm volatile("mma.sync.aligned.m16n8k16.row.col.f32.bf16.bf16.f32 " \
        "{%0,%1,%2,%3}, {%4,%5,%6,%7}, {%8,%9}, {%0,%1,%2,%3};" \
        : "+f"((d)[0]),"+f"((d)[1]),"+f"((d)[2]),"+f"((d)[3]) \
        : "r"((a)[0]),"r"((a)[1]),"r"((a)[2]),"r"((a)[3]), "r"((b)[0]),"r"((b)[1]))

__device__ __forceinline__ void split2(float x, bf16& h, bf16& m)
{
    h = __float2bfloat16(x);
    float r = x - __bfloat162float(h);
    m = __float2bfloat16(r);
}

// ---------------- weight transpose + split2: W[K,N] fp32 -> [N,K] bf16 x2 ---
__global__ void wsplit_kernel(const float* __restrict__ W, bf16* __restrict__ Oh,
                              bf16* __restrict__ Om, int K, int N)
{
    __shared__ float t[32][33];
    int k0 = blockIdx.x * 32, n0 = blockIdx.y * 32;
    int tx = threadIdx.x, ty = threadIdx.y;      // (32, 8)
    const float* Wp = W + (size_t)blockIdx.z * K * N;
    size_t ob = (size_t)blockIdx.z * N * K;
    #pragma unroll
    for (int r = ty; r < 32; r += 8)
        t[r][tx] = Wp[(size_t)(k0 + r) * N + n0 + tx];
    __syncthreads();
    #pragma unroll
    for (int r = ty; r < 32; r += 8) {
        float x = t[tx][r];
        bf16 h, m; split2(x, h, m);
        size_t o = ob + (size_t)(n0 + r) * K + k0 + tx;
        Oh[o] = h; Om[o] = m;
    }
}

// ---------------- im2col (fp32) ---------------------------------------------
__global__ void im2col_kernel(const float* __restrict__ inp, float* __restrict__ PT)
{
    size_t idx = (size_t)blockIdx.x * 256 + threadIdx.x;
    const size_t total = (size_t)BATCH * NPATCH * DIM;
    if (idx >= total) return;
    int k = (int)(idx % DIM);
    int p = (int)((idx / DIM) % NPATCH);
    int b = (int)(idx / ((size_t)DIM * NPATCH));
    int c  = k / (PSZ*PSZ);
    int py = (k / PSZ) % PSZ;
    int px = k % PSZ;
    int gy = p / GRIDSZ, gx = p % GRIDSZ;
    PT[idx] = inp[(((size_t)b*CCH + c)*IMGSZ + (size_t)gy*PSZ + py)*IMGSZ + gx*PSZ + px];
}

// ---------------- FFMA2 SGEMM (fp32 path) -----------------------------------
// BIT-EXACT k-ascending fma.rn.f32x2 chain per element; frozen epilogue order.
// K-tile 16, A staged as duplicated (a,a) pairs (kills the mov.b64 dup).
// mode 0: plain; 1: +residual; 2: tanh-GELU
#define SMEM_F32 49152   // [2][16][256] As2 (32KB) + [2][16][128] Bs (16KB)

__global__ void __launch_bounds__(256, 2)
gemm128_kernel(const float* __restrict__ A, const float* __restrict__ Bm,
               const float* __restrict__ bias, const float* __restrict__ res,
               float* __restrict__ C, int M, int N, int K, int mode)
{
    extern __shared__ float smf[];
    float* As2 = smf;                 // [2][16][256]
    float* Bs  = smf + 2*16*256;      // [2][16][128]
    int tid = threadIdx.x;
    int tx = tid & 15, ty = tid >> 4;
    int m0 = blockIdx.y * 128, n0 = blockIdx.x * 128;
    int ar = tid >> 1, ak8 = (tid & 1) * 8;   // A: row, k-offset (8 floats)
    int br8 = tid >> 5, bc = (tid & 31) * 4;  // B: k-row base, col offset
    bool avalid = (m0 + ar) < M;
    bool bvalid = (n0 + bc) < N;
    const float* Aptr = A + (size_t)(m0 + ar) * K + ak8;
    const float* Bptr = Bm + (size_t)br8 * N + n0 + bc;
    const float4 z4 = make_float4(0.f,0.f,0.f,0.f);
    int T = K >> 4;

    float4 av0 = avalid ? *(const float4*)Aptr        : z4;
    float4 av1 = avalid ? *(const float4*)(Aptr + 4)  : z4;
    float4 bv0 = bvalid ? *(const float4*)Bptr                 : z4;
    float4 bv1 = bvalid ? *(const float4*)(Bptr + (size_t)8*N) : z4;
    {
        float va[8] = {av0.x,av0.y,av0.z,av0.w,av1.x,av1.y,av1.z,av1.w};
        #pragma unroll
        for (int q = 0; q < 8; q++)
            *(float2*)&As2[(0*16 + ak8 + q)*256 + 2*ar] = make_float2(va[q], va[q]);
        *(float4*)&Bs[(0*16 + br8)*128 + bc]     = bv0;
        *(float4*)&Bs[(0*16 + br8 + 8)*128 + bc] = bv1;
    }
    __syncthreads();

    unsigned long long acc2[8][4];
    #pragma unroll
    for (int i = 0; i < 8; i++)
        #pragma unroll
        for (int j = 0; j < 4; j++) acc2[i][j] = 0ull;

    for (int t = 0; t < T; t++) {
        int cur = t & 1;
        if (t + 1 < T) {
            const float* Ap = Aptr + (size_t)(t+1)*16;
            const float* Bp = Bptr + (size_t)(t+1)*16*N;
            av0 = avalid ? *(const float4*)Ap       : z4;
            av1 = avalid ? *(const float4*)(Ap + 4) : z4;
            bv0 = bvalid ? *(const float4*)Bp                 : z4;
            bv1 = bvalid ? *(const float4*)(Bp + (size_t)8*N) : z4;
        }
        #pragma unroll
        for (int kk = 0; kk < 16; kk++) {
            const ulonglong2* pa = (const ulonglong2*)&As2[(cur*16 + kk)*256 + ty*16];
            ulonglong2 p0 = pa[0], p1 = pa[1], p2 = pa[2], p3 = pa[3];
            unsigned long long a2[8] = {p0.x, p0.y, p1.x, p1.y, p2.x, p2.y, p3.x, p3.y};
            const ulonglong2* pb = (const ulonglong2*)&Bs[(cur*16 + kk)*128 + tx*8];
            ulonglong2 q0 = pb[0], q1 = pb[1];
            unsigned long long b2[4] = {q0.x, q0.y, q1.x, q1.y};
            #pragma unroll
            for (int i = 0; i < 8; i++)
                #pragma unroll
                for (int j = 0; j < 4; j++)
                    asm("fma.rn.f32x2 %0, %1, %2, %0;"
                        : "+l"(acc2[i][j]) : "l"(a2[i]), "l"(b2[j]));
        }
        if (t + 1 < T) {
            int nxt = cur ^ 1;
            float va[8] = {av0.x,av0.y,av0.z,av0.w,av1.x,av1.y,av1.z,av1.w};
            #pragma unroll
            for (int q = 0; q < 8; q++)
                *(float2*)&As2[(nxt*16 + ak8 + q)*256 + 2*ar] = make_float2(va[q], va[q]);
            *(float4*)&Bs[(nxt*16 + br8)*128 + bc]     = bv0;
            *(float4*)&Bs[(nxt*16 + br8 + 8)*128 + bc] = bv1;
            __syncthreads();
        }
    }
    #pragma unroll
    for (int i = 0; i < 8; i++) {
        int m = m0 + ty*8 + i;
        if (m >= M) continue;
        float c[8];
        #pragma unroll
        for (int j = 0; j < 4; j++)
            asm("mov.b64 {%0, %1}, %2;" : "=f"(c[2*j]), "=f"(c[2*j+1]) : "l"(acc2[i][j]));
        #pragma unroll
        for (int j = 0; j < 8; j++) {
            int n = n0 + tx*8 + j;
            if (n >= N) continue;
            float v = c[j] + bias[n];
            if (mode == 1) {
                v += res[(size_t)m*N + n];
            } else if (mode == 2) {
                float x = v;
                v = 0.5f * x * (1.0f + tanhf(0.7978845608028654f * (x + 0.044715f*x*x*x)));
            }
            C[(size_t)m*N + n] = v;
        }
    }
}

// ---------------- mma.sync bf16 2-split/3-product GEMM (layers > SELL) ------
#define APITCH   144
#define SPLIT_SZ (128*APITCH)          // 18432
#define STG_SZ   (4*SPLIT_SZ)          // 73728
#define SMEM_MMA (2*STG_SZ)            // 147456

__global__ void __launch_bounds__(512, 1)
gemm_mma(const bf16* __restrict__ Ah, const bf16* __restrict__ Am,
         const bf16* __restrict__ Bh, const bf16* __restrict__ Bm,
         const float* __restrict__ bias, const float* __restrict__ res,
         float* __restrict__ Cf, bf16* __restrict__ Ch, bf16* __restrict__ Cm,
         int M, int N, int K, int mode)
{
    extern __shared__ char smem[];
    uint32_t sb = smem_u32(smem);
    int tid = threadIdx.x, lane = tid & 31, warp = tid >> 5;
    int wm = warp >> 2, wn = warp & 3;         // 4 x 4 warps, 32x32 tile each
    int m0 = blockIdx.y * 128, n0 = blockIdx.x * 128;

    float acc[2][4][4] = {};
    int lr = lane & 15;
    int lk = (lane >> 4) * 16;
    int T = K >> 6;                            // K/64 tiles

    auto issue_stage = [&](int buf, int kc) {
        uint32_t base = sb + buf * STG_SZ;
        #pragma unroll
        for (int j = 0; j < 2; j++) {
            int u = j * 512 + tid;
            int row = u >> 3, q = u & 7;       // 128 rows x 8 quads(16B)
            uint32_t d = base + row*APITCH + q*16;
            size_t goff = (size_t)row * K + kc + q*8;
            int asz = (m0 + row < M) ? 16 : 0;
            cpasync16(d + 0*SPLIT_SZ, Ah + (size_t)m0*K + goff, asz);
            cpasync16(d + 1*SPLIT_SZ, Am + (size_t)m0*K + goff, asz);
            cpasync16(d + 2*SPLIT_SZ, Bh + (size_t)n0*K + goff, 16);
            cpasync16(d + 3*SPLIT_SZ, Bm + (size_t)n0*K + goff, 16);
        }
    };

    issue_stage(0, 0);
    CP_COMMIT();

    for (int t = 0; t < T; t++) {
        if (t + 1 < T) issue_stage((t + 1) & 1, (t + 1) * 64);
        CP_COMMIT();
        CP_WAIT1();
        __syncthreads();

        uint32_t stg = sb + (t & 1) * STG_SZ;
        #pragma unroll
        for (int kh = 0; kh < 4; kh++) {
            int kb = kh * 32 + lk;
            uint32_t afr[2][2][4], bfr[2][4][2];
            #pragma unroll
            for (int s = 0; s < 2; s++) {
                #pragma unroll
                for (int mt = 0; mt < 2; mt++) {
                    uint32_t ad = stg + s*SPLIT_SZ + (uint32_t)(wm*32 + mt*16 + lr)*APITCH + kb;
                    LDSM4(afr[s][mt][0], afr[s][mt][1], afr[s][mt][2], afr[s][mt][3], ad);
                }
                #pragma unroll
                for (int np = 0; np < 2; np++) {
                    uint32_t r0, r1, r2, r3;
                    uint32_t bd = stg + (2+s)*SPLIT_SZ + (uint32_t)(wn*32 + np*16 + lr)*APITCH + kb;
                    LDSM4(r0, r1, r2, r3, bd);
                    bfr[s][np*2+0][0] = r0; bfr[s][np*2+0][1] = r2;
                    bfr[s][np*2+1][0] = r1; bfr[s][np*2+1][1] = r3;
                }
            }
            // products: hh, hm, mh
            #pragma unroll
            for (int p = 0; p < 3; p++) {
                int sa = (p == 2) ? 1 : 0;
                int sbp = (p == 1) ? 1 : 0;
                #pragma unroll
                for (int mt = 0; mt < 2; mt++)
                    #pragma unroll
                    for (int nt = 0; nt < 4; nt++)
                        MMA16816(acc[mt][nt], afr[sa][mt], bfr[sbp][nt]);
            }
        }
        __syncthreads();
    }

    // ---- epilogue
    #pragma unroll
    for (int mt = 0; mt < 2; mt++) {
        #pragma unroll
        for (int h2 = 0; h2 < 2; h2++) {
            int rr = m0 + wm*32 + mt*16 + (lane >> 2) + h2*8;
            if (rr >= M) continue;
            #pragma unroll
            for (int nt = 0; nt < 4; nt++) {
                int c = n0 + wn*32 + nt*8 + (lane & 3)*2;
                float v0 = acc[mt][nt][h2*2+0] + bias[c];
                float v1 = acc[mt][nt][h2*2+1] + bias[c+1];
                size_t o = (size_t)rr * N + c;
                if (mode == 1) { v0 += res[o]; v1 += res[o+1]; }
                if (mode <= 1) {
                    float2 v; v.x = v0; v.y = v1;
                    *(float2*)&Cf[o] = v;
                } else {
                    float g0 = 0.5f*v0*(1.0f + tanhf(0.7978845608028654f*(v0 + 0.044715f*v0*v0*v0)));
                    float g1 = 0.5f*v1*(1.0f + tanhf(0.7978845608028654f*(v1 + 0.044715f*v1*v1*v1)));
                    bf16 h0, m0b, h1, m1b;
                    split2(g0, h0, m0b);
                    split2(g1, h1, m1b);
                    *(__nv_bfloat162*)&Ch[o] = __nv_bfloat162(h0, h1);
                    *(__nv_bfloat162*)&Cm[o] = __nv_bfloat162(m0b, m1b);
                }
            }
        }
    }
}

// ---------------- layernorm: fp32 out and/or split2 out ---------------------
__global__ void ln_kernel(const float* __restrict__ X, const float* __restrict__ g,
                          const float* __restrict__ b, float* __restrict__ Yf,
                          bf16* __restrict__ Yh, bf16* __restrict__ Ym)
{
    int row = blockIdx.x;
    const float* x = X + (size_t)row * DIM;
    __shared__ float red[256];
    int tid = threadIdx.x;
    float v0 = x[tid], v1 = x[tid+256], v2 = x[tid+512];
    red[tid] = v0 + v1 + v2;
    __syncthreads();
    for (int o = 128; o > 0; o >>= 1) { if (tid < o) red[tid] += red[tid+o]; __syncthreads(); }
    float mean = red[0] * (1.0f / DIM);
    __syncthreads();
    float d0 = v0-mean, d1 = v1-mean, d2 = v2-mean;
    red[tid] = d0*d0 + d1*d1 + d2*d2;
    __syncthreads();
    for (int o = 128; o > 0; o >>= 1) { if (tid < o) red[tid] += red[tid+o]; __syncthreads(); }
    float rstd = 1.0f / sqrtf(red[0] * (1.0f / DIM) + LNEPS);
    size_t base = (size_t)row * DIM;
    float o0 = d0*rstd*g[tid]     + b[tid];
    float o1 = d1*rstd*g[tid+256] + b[tid+256];
    float o2 = d2*rstd*g[tid+512] + b[tid+512];
    if (Yf) { Yf[base+tid] = o0; Yf[base+tid+256] = o1; Yf[base+tid+512] = o2; }
    if (Yh) {
        bf16 h, m;
        split2(o0, h, m); Yh[base+tid]     = h; Ym[base+tid]     = m;
        split2(o1, h, m); Yh[base+tid+256] = h; Ym[base+tid+256] = m;
        split2(o2, h, m); Yh[base+tid+512] = h; Ym[base+tid+512] = m;
    }
}

// ---------------- assemble X = [cls | patches] + pos ------------------------
__global__ void assemble_kernel(const float* __restrict__ PE, const float* __restrict__ cls,
                                const float* __restrict__ pos, float* __restrict__ X)
{
    size_t idx = (size_t)blockIdx.x * 256 + threadIdx.x;
    const size_t total = (size_t)BATCH * LFULL * DIM;
    if (idx >= total) return;
    int d = (int)(idx % DIM);
    int r = (int)((idx / DIM) % LFULL);
    int b = (int)(idx / ((size_t)LFULL * DIM));
    float v = (r == 0) ? cls[d] : PE[((size_t)b*NPATCH + (r-1))*DIM + d];
    X[idx] = v + pos[(size_t)r*DIM + d];
}

// ---------------- tiled attention v3: register microtiles, LDS-lean ---------
#define QT 32
#define KC 32
__global__ void __launch_bounds__(256)
attn3_kernel(const float* __restrict__ QKV, float* __restrict__ Of,
             bf16* __restrict__ Oh, bf16* __restrict__ Om, int L)
{
    int q0b = blockIdx.x * QT;
    int h  = blockIdx.y;
    int b  = blockIdx.z;
    __shared__ float Qt[DH][34];                 // Q transposed [d][q]
    __shared__ __align__(16) float KVu[64*36];   // union: Kt[d][kk] pitch 36 / Vs[kk][d] pitch 68
    __shared__ float sc[QT][224];
    int tid = threadIdx.x;
    const size_t rs = 3 * DIM;
    const float* base = QKV + (size_t)b * L * rs;

    // load Q transposed
    for (int i = tid; i < QT*DH; i += 256) {
        int qq = i >> 6, d = i & 63;
        Qt[d][qq] = (q0b + qq < L) ? base[(size_t)(q0b+qq)*rs + h*DH + d] : 0.f;
    }

    int ty = tid >> 4, tx = tid & 15;            // score: 2q x 2k ; V: 2q x 4d
    // ---- score pass
    for (int kc = 0; kc < L; kc += KC) {
        __syncthreads();
        for (int i = tid; i < KC*DH; i += 256) {
            int kk = i >> 6, d = i & 63;
            KVu[d*36 + kk] = (kc + kk < L) ? base[(size_t)(kc+kk)*rs + DIM + h*DH + d] : 0.f;
        }
        __syncthreads();
        float a00 = 0.f, a01 = 0.f, a10 = 0.f, a11 = 0.f;
        #pragma unroll 8
        for (int d = 0; d < DH; d++) {
            float2 qv = *(const float2*)&Qt[d][2*ty];
            float k0 = KVu[d*36 + 2*tx];
            float k1 = KVu[d*36 + 2*tx + 1];
            a00 += qv.x * k0; a01 += qv.x * k1;
            a10 += qv.y * k0; a11 += qv.y * k1;
        }
        int k0i = kc + 2*tx, k1i = k0i + 1;
        sc[2*ty+0][k0i] = (k0i < L) ? a00 * 0.125f : -1e30f;
        sc[2*ty+0][k1i] = (k1i < L) ? a01 * 0.125f : -1e30f;
        sc[2*ty+1][k0i] = (k0i < L) ? a10 * 0.125f : -1e30f;
        sc[2*ty+1][k1i] = (k1i < L) ? a11 * 0.125f : -1e30f;
    }
    __syncthreads();
    // ---- softmax (identical code to previous rounds)
    int wid = tid >> 5, lane = tid & 31;
    for (int qq = wid; qq < QT; qq += 8) {
        float mx = -1e30f;
        for (int k = lane; k < L; k += 32) mx = fmaxf(mx, sc[qq][k]);
        for (int o = 16; o; o >>= 1) mx = fmaxf(mx, __shfl_xor_sync(~0u, mx, o));
        float sum = 0.f;
        for (int k = lane; k < L; k += 32) { float e = expf(sc[qq][k] - mx); sc[qq][k] = e; sum += e; }
        for (int o = 16; o; o >>= 1) sum += __shfl_xor_sync(~0u, sum, o);
        float inv = 1.0f / sum;
        for (int k = lane; k < L; k += 32) sc[qq][k] *= inv;
    }
    // ---- V pass: thread owns rows (2*ty, 2*ty+1) x cols (4*tx .. 4*tx+3)
    float ov0[4] = {}, ov1[4] = {};
    int d0 = 4 * tx;
    for (int kc = 0; kc < L; kc += KC) {
        __syncthreads();
        for (int i = tid; i < KC*DH; i += 256) {
            int kk = i >> 6, dd = i & 63;
            KVu[kk*68 + dd] = (kc + kk < L) ? base[(size_t)(kc+kk)*rs + 2*DIM + h*DH + dd] : 0.f;
        }
        __syncthreads();
        int kmax = min(KC, L - kc);
        for (int kk = 0; kk < kmax; kk++) {
            float s0 = sc[2*ty+0][kc+kk];
            float s1 = sc[2*ty+1][kc+kk];
            float4 v = *(const float4*)&KVu[kk*68 + d0];
            ov0[0] += s0 * v.x; ov0[1] += s0 * v.y; ov0[2] += s0 * v.z; ov0[3] += s0 * v.w;
            ov1[0] += s1 * v.x; ov1[1] += s1 * v.y; ov1[2] += s1 * v.z; ov1[3] += s1 * v.w;
        }
    }
    #pragma unroll
    for (int i = 0; i < 2; i++) {
        int q = q0b + 2*ty + i;
        if (q >= L) continue;
        const float* src = (i == 0) ? ov0 : ov1;
        size_t o = ((size_t)(b*L + q))*DIM + h*DH + d0;
        if (Of) {
            *(float4*)&Of[o] = make_float4(src[0], src[1], src[2], src[3]);
        } else {
            bf16 h0, m0v, h1, m1v;
            #pragma unroll
            for (int j = 0; j < 4; j += 2) {
                split2(src[j],   h0, m0v);
                split2(src[j+1], h1, m1v);
                *(__nv_bfloat162*)&Oh[o + j] = __nv_bfloat162(h0, h1);
                *(__nv_bfloat162*)&Om[o + j] = __nv_bfloat162(m0v, m1v);
            }
        }
    }
}

// ---------------- cosine similarity (fp64) ----------------------------------
__global__ void sim_kernel(const float* __restrict__ X, float* __restrict__ SIM)
{
    int p = blockIdx.x, b = blockIdx.y;
    const float* cls = X + (size_t)b * LFULL * DIM;
    const float* pt  = X + ((size_t)b*LFULL + 1 + p) * DIM;
    int tid = threadIdx.x;
    double dot = 0.0, nc = 0.0, np = 0.0;
    for (int d = tid; d < DIM; d += 128) {
        double c = (double)cls[d], v = (double)pt[d];
        dot += c*v; nc += c*c; np += v*v;
    }
    __shared__ double r1[128], r2[128], r3[128];
    r1[tid] = dot; r2[tid] = nc; r3[tid] = np;
    __syncthreads();
    for (int o = 64; o > 0; o >>= 1) {
        if (tid < o) { r1[tid]+=r1[tid+o]; r2[tid]+=r2[tid+o]; r3[tid]+=r3[tid+o]; }
        __syncthreads();
    }
    if (tid == 0) {
        double den = sqrt(r2[0]) * sqrt(r3[0]);
        den = den > 1e-8 ? den : 1e-8;
        SIM[b*NPATCH + p] = (float)(r1[0] / den);
    }
}

// ---------------- stable top-K ----------------------------------------------
__global__ void topk_kernel(const float* __restrict__ SIM, int* __restrict__ IDX)
{
    int b = blockIdx.x;
    __shared__ float s[NPATCH];
    int tid = threadIdx.x;
    if (tid < NPATCH) s[tid] = SIM[b*NPATCH + tid];
    __syncthreads();
    if (tid < NPATCH) {
        float si = s[tid];
        int rank = 0;
        for (int j = 0; j < NPATCH; j++) {
            float sj = s[j];
            rank += (sj > si) || (sj == si && j < tid);
        }
        if (rank < KEEP) IDX[b*KEEP + rank] = tid;
    }
}

// ---------------- gather ----------------------------------------------------
__global__ void gather_kernel(const float* __restrict__ X, const int* __restrict__ IDX,
                              float* __restrict__ X2)
{
    size_t idx = (size_t)blockIdx.x * 256 + threadIdx.x;
    const size_t total = (size_t)BATCH * LPRUNE * DIM;
    if (idx >= total) return;
    int d = (int)(idx % DIM);
    int r = (int)((idx / DIM) % LPRUNE);
    int b = (int)(idx / ((size_t)LPRUNE * DIM));
    int src = (r == 0) ? 0 : (1 + IDX[b*KEEP + (r-1)]);
    X2[idx] = X[((size_t)b*LFULL + src)*DIM + d];
}

// ---------------- host orchestration ----------------------------------------
extern "C" void kernel_launch(void* const* d_in, const int* in_sizes, int n_in,
                              void* d_out, int out_size)
{
    const float* inputs    = (const float*)d_in[0];
    const float* patch_w   = (const float*)d_in[1];
    const float* patch_b   = (const float*)d_in[2];
    const float* cls_token = (const float*)d_in[3];
    const float* pos_embed = (const float*)d_in[4];
    const float* qkv_w     = (const float*)d_in[5];
    const float* qkv_b     = (const float*)d_in[6];
    const float* proj_w    = (const float*)d_in[7];
    const float* proj_b    = (const float*)d_in[8];
    const float* ln1_g     = (const float*)d_in[9];
    const float* ln1_b     = (const float*)d_in[10];
    const float* ln2_g     = (const float*)d_in[11];
    const float* ln2_b     = (const float*)d_in[12];
    const float* mlp_w1    = (const float*)d_in[13];
    const float* mlp_b1    = (const float*)d_in[14];
    const float* mlp_w2    = (const float*)d_in[15];
    const float* mlp_b2    = (const float*)d_in[16];
    const float* norm_g    = (const float*)d_in[17];
    const float* norm_b    = (const float*)d_in[18];
    const float* head_w    = (const float*)d_in[19];
    const float* head_b    = (const float*)d_in[20];

    float *X, *X2, *Hf, *QKV, *Ofp, *M1f, *PT, *PE, *SIM; int* IDX;
    bf16 *AH, *AM, *OH, *OM, *M1H, *M1M, *WH, *WM;
    cudaGetSymbolAddress((void**)&X,   g_X);
    cudaGetSymbolAddress((void**)&X2,  g_X2);
    cudaGetSymbolAddress((void**)&Hf,  g_Hf);
    cudaGetSymbolAddress((void**)&QKV, g_QKV);
    cudaGetSymbolAddress((void**)&Ofp, g_O);
    cudaGetSymbolAddress((void**)&M1f, g_M1);
    cudaGetSymbolAddress((void**)&PT,  g_PT);
    cudaGetSymbolAddress((void**)&PE,  g_PE);
    cudaGetSymbolAddress((void**)&SIM, g_SIM);
    cudaGetSymbolAddress((void**)&IDX, g_IDX);
    cudaGetSymbolAddress((void**)&AH,  g_AH);  cudaGetSymbolAddress((void**)&AM, g_AM);
    cudaGetSymbolAddress((void**)&OH,  g_OH);  cudaGetSymbolAddress((void**)&OM, g_OM);
    cudaGetSymbolAddress((void**)&M1H, g_M1H); cudaGetSymbolAddress((void**)&M1M, g_M1M);
    cudaGetSymbolAddress((void**)&WH,  g_WH);  cudaGetSymbolAddress((void**)&WM, g_WM);

    cudaFuncSetAttribute(gemm_mma, cudaFuncAttributeMaxDynamicSharedMemorySize, SMEM_MMA);
    cudaFuncSetAttribute(gemm128_kernel, cudaFuncAttributeMaxDynamicSharedMemorySize, SMEM_F32);

    // ---- weight prep for mma layers (transpose + split2)
    {
        dim3 blk(32, 8);
        wsplit_kernel<<<dim3(24, 72, 12), blk>>>(qkv_w,  WH+OFF_QKV,  WM+OFF_QKV,  768, 2304);
        wsplit_kernel<<<dim3(24, 24, 12), blk>>>(proj_w, WH+OFF_PROJ, WM+OFF_PROJ, 768, 768);
        wsplit_kernel<<<dim3(24, 96, 12), blk>>>(mlp_w1, WH+OFF_W1,   WM+OFF_W1,   768, 3072);
        wsplit_kernel<<<dim3(96, 24, 12), blk>>>(mlp_w2, WH+OFF_W2,   WM+OFF_W2,   3072, 768);
    }

    // ---- patch embedding (fp32 FFMA2 path — bit-exact chain)
    {
        size_t total = (size_t)BATCH * NPATCH * DIM;
        im2col_kernel<<<(unsigned)((total + 255)/256), 256>>>(inputs, PT);
        dim3 g(6, 49);
        gemm128_kernel<<<g, 256, SMEM_F32>>>(PT, patch_w, patch_b, nullptr, PE,
                                             BATCH*NPATCH, DIM, DIM, 0);
        size_t tot2 = (size_t)BATCH * LFULL * DIM;
        assemble_kernel<<<(unsigned)((tot2 + 255)/256), 256>>>(PE, cls_token, pos_embed, X);
    }

    float* cur = X;
    int L = LFULL;
    for (int n = 0; n < NLAYER; n++) {
        int M = BATCH * L;
        int Mt = (M + 127) / 128;
        if (n <= SELL) {
            // ======== fp32 FFMA2 path (bit-exact frozen numerics; selection-safe)
            ln_kernel<<<M, 256>>>(cur, ln1_g + (size_t)n*DIM, ln1_b + (size_t)n*DIM,
                                  Hf, nullptr, nullptr);
            gemm128_kernel<<<dim3(18, Mt), 256, SMEM_F32>>>(Hf, qkv_w + (size_t)n*DIM*3*DIM,
                qkv_b + (size_t)n*3*DIM, nullptr, QKV, M, 3*DIM, DIM, 0);
            {
                dim3 g((L + QT - 1)/QT, NHEAD, BATCH);
                attn3_kernel<<<g, 256>>>(QKV, Ofp, nullptr, nullptr, L);
            }
            gemm128_kernel<<<dim3(6, Mt), 256, SMEM_F32>>>(Ofp, proj_w + (size_t)n*DIM*DIM,
                proj_b + (size_t)n*DIM, cur, cur, M, DIM, DIM, 1);
            ln_kernel<<<M, 256>>>(cur, ln2_g + (size_t)n*DIM, ln2_b + (size_t)n*DIM,
                                  Hf, nullptr, nullptr);
            gemm128_kernel<<<dim3(24, Mt), 256, SMEM_F32>>>(Hf, mlp_w1 + (size_t)n*DIM*DFFN,
                mlp_b1 + (size_t)n*DFFN, nullptr, M1f, M, DFFN, DIM, 2);
            gemm128_kernel<<<dim3(6, Mt), 256, SMEM_F32>>>(M1f, mlp_w2 + (size_t)n*DFFN*DIM,
                mlp_b2 + (size_t)n*DIM, cur, cur, M, DIM, DFFN, 1);
            if (n == SELL) {
                dim3 gs(NPATCH, BATCH);
                sim_kernel<<<gs, 128>>>(cur, SIM);
                topk_kernel<<<BATCH, 256>>>(SIM, IDX);
                size_t tot = (size_t)BATCH * LPRUNE * DIM;
                gather_kernel<<<(unsigned)((tot + 255)/256), 256>>>(cur, IDX, X2);
                cur = X2;
                L = LPRUNE;
            }
        } else {
            // ======== bf16 mma path (post-selection)
            ln_kernel<<<M, 256>>>(cur, ln1_g + (size_t)n*DIM, ln1_b + (size_t)n*DIM,
                                  nullptr, AH, AM);
            gemm_mma<<<dim3(18, Mt), 512, SMEM_MMA>>>(AH, AM,
                WH+OFF_QKV + (size_t)n*2304*768, WM+OFF_QKV + (size_t)n*2304*768,
                qkv_b + (size_t)n*3*DIM, nullptr, QKV, nullptr, nullptr, M, 3*DIM, DIM, 0);
            {
                dim3 g((L + QT - 1)/QT, NHEAD, BATCH);
                attn3_kernel<<<g, 256>>>(QKV, nullptr, OH, OM, L);
            }
            gemm_mma<<<dim3(6, Mt), 512, SMEM_MMA>>>(OH, OM,
                WH+OFF_PROJ + (size_t)n*768*768, WM+OFF_PROJ + (size_t)n*768*768,
                proj_b + (size_t)n*DIM, cur, cur, nullptr, nullptr, M, DIM, DIM, 1);
            ln_kernel<<<M, 256>>>(cur, ln2_g + (size_t)n*DIM, ln2_b + (size_t)n*DIM,
                                  nullptr, AH, AM);
            gemm_mma<<<dim3(24, Mt), 512, SMEM_MMA>>>(AH, AM,
                WH+OFF_W1 + (size_t)n*3072*768, WM+OFF_W1 + (size_t)n*3072*768,
                mlp_b1 + (size_t)n*DFFN, nullptr, nullptr, M1H, M1M, M, DFFN, DIM, 2);
            gemm_mma<<<dim3(6, Mt), 512, SMEM_MMA>>>(M1H, M1M,
                WH+OFF_W2 + (size_t)n*768*3072, WM+OFF_W2 + (size_t)n*768*3072,
                mlp_b2 + (size_t)n*DIM, cur, cur, nullptr, nullptr, M, DIM, DFFN, 1);
        }
    }

    // ---- final LN + head (fp32 FFMA2 path)
    {
        int M = BATCH * LPRUNE;
        ln_kernel<<<M, 256>>>(cur, norm_g, norm_b, Hf, nullptr, nullptr);
        dim3 g(1, (M + 127)/128);
        gemm128_kernel<<<g, 256, SMEM_F32>>>(Hf, head_w, head_b, nullptr, (float*)d_out,
                                             M, NCLS, DIM, 0);
    }
}

// round 15
// speedup vs baseline: 1.1951x; 1.0022x over previous
#include <cuda_runtime.h>
#include <cuda_bf16.h>
#include <math.h>
#include <stdint.h>

#define BATCH   32
#define CCH     3
#define IMGSZ   224
#define PSZ     16
#define GRIDSZ  14
#define NPATCH  196
#define DIM     768
#define NHEAD   12
#define NLAYER  12
#define DFFN    3072
#define DH      64
#define NCLS    100
#define SELL    3
#define KEEP    137
#define LFULL   197
#define LPRUNE  138
#define LNEPS   1e-6f

typedef __nv_bfloat16 bf16;

// ---------------- weight arena offsets (bf16 [N,K] transposed) --------------
#define OFF_QKV   0ull
#define OFF_PROJ  (OFF_QKV  + 12ull*2304*768)
#define OFF_W1    (OFF_PROJ + 12ull*768*768)
#define OFF_W2    (OFF_W1   + 12ull*3072*768)
#define W_TOTAL   (OFF_W2   + 12ull*768*3072)

// ---------------- scratch (static device globals) ---------------------------
__device__ __align__(16) float g_X  [BATCH*LFULL*DIM];
__device__ __align__(16) float g_X2 [BATCH*LFULL*DIM];
__device__ __align__(16) float g_Hf [BATCH*LFULL*DIM];
__device__ __align__(16) float g_QKV[BATCH*LFULL*3*DIM];
__device__ __align__(16) float g_O  [BATCH*LFULL*DIM];
__device__ __align__(16) float g_M1 [BATCH*LFULL*DFFN];
__device__ __align__(16) float g_PT [BATCH*NPATCH*DIM];
__device__ __align__(16) float g_PE [BATCH*NPATCH*DIM];
__device__ __align__(16) float g_SIM[BATCH*NPATCH];
__device__               int   g_IDX[BATCH*KEEP];
// bf16 split activations (mma path, layers > SELL): hi + mid only
__device__ __align__(16) bf16 g_AH [BATCH*LFULL*DIM];
__device__ __align__(16) bf16 g_AM [BATCH*LFULL*DIM];
__device__ __align__(16) bf16 g_OH [BATCH*LFULL*DIM];
__device__ __align__(16) bf16 g_OM [BATCH*LFULL*DIM];
__device__ __align__(16) bf16 g_M1H[BATCH*LFULL*DFFN];
__device__ __align__(16) bf16 g_M1M[BATCH*LFULL*DFFN];
// bf16 split transposed weights (hi + mid)
__device__ __align__(16) bf16 g_WH[W_TOTAL];
__device__ __align__(16) bf16 g_WM[W_TOTAL];

// ---------------- helpers ----------------------------------------------------
__device__ __forceinline__ uint32_t smem_u32(const void* p){
    uint32_t a;
    asm("{ .reg .u64 t; cvta.to.shared.u64 t, %1; cvt.u32.u64 %0, t; }" : "=r"(a) : "l"(p));
    return a;
}
__device__ __forceinline__ void cpasync16(uint32_t dst, const void* src, int sz){
    asm volatile("cp.async.cg.shared.global [%0], [%1], 16, %2;"
                 :: "r"(dst), "l"(src), "r"(sz));
}
#define CP_COMMIT() asm volatile("cp.async.commit_group;" ::: "memory")
#define CP_WAIT2()  asm volatile("cp.async.wait_group 2;"  ::: "memory")

#define LDSM4(r0,r1,r2,r3,addr) \
    asm volatile("ldmatrix.sync.aligned.m8n8.x4.shared.b16 {%0,%1,%2,%3}, [%4];" \
        : "=r"(r0),"=r"(r1),"=r"(r2),"=r"(r3) : "r"(addr))

#define MMA16816(d, a, b) \
    asm volatile("mma.sync.aligned.m16n8k16.row.col.f32.bf16.bf16.f32 " \
        "{%0,%1,%2,%3}, {%4,%5,%6,%7}, {%8,%9}, {%0,%1,%2,%3};" \
        : "+f"((d)[0]),"+f"((d)[1]),"+f"((d)[2]),"+f"((d)[3]) \
        : "r"((a)[0]),"r"((a)[1]),"r"((a)[2]),"r"((a)[3]), "r"((b)[0]),"r"((b)[1]))

__device__ __forceinline__ void split2(float x, bf16& h, bf16& m)
{
    h = __float2bfloat16(x);
    float r = x - __bfloat162float(h);
    m = __float2bfloat16(r);
}

// ---------------- weight transpose + split2: W[K,N] fp32 -> [N,K] bf16 x2 ---
__global__ void wsplit_kernel(const float* __restrict__ W, bf16* __restrict__ Oh,
                              bf16* __restrict__ Om, int K, int N)
{
    __shared__ float t[32][33];
    int k0 = blockIdx.x * 32, n0 = blockIdx.y * 32;
    int tx = threadIdx.x, ty = threadIdx.y;      // (32, 8)
    const float* Wp = W + (size_t)blockIdx.z * K * N;
    size_t ob = (size_t)blockIdx.z * N * K;
    #pragma unroll
    for (int r = ty; r < 32; r += 8)
        t[r][tx] = Wp[(size_t)(k0 + r) * N + n0 + tx];
    __syncthreads();
    #pragma unroll
    for (int r = ty; r < 32; r += 8) {
        float x = t[tx][r];
        bf16 h, m; split2(x, h, m);
        size_t o = ob + (size_t)(n0 + r) * K + k0 + tx;
        Oh[o] = h; Om[o] = m;
    }
}

// ---------------- im2col (fp32) ---------------------------------------------
__global__ void im2col_kernel(const float* __restrict__ inp, float* __restrict__ PT)
{
    size_t idx = (size_t)blockIdx.x * 256 + threadIdx.x;
    const size_t total = (size_t)BATCH * NPATCH * DIM;
    if (idx >= total) return;
    int k = (int)(idx % DIM);
    int p = (int)((idx / DIM) % NPATCH);
    int b = (int)(idx / ((size_t)DIM * NPATCH));
    int c  = k / (PSZ*PSZ);
    int py = (k / PSZ) % PSZ;
    int px = k % PSZ;
    int gy = p / GRIDSZ, gx = p % GRIDSZ;
    PT[idx] = inp[(((size_t)b*CCH + c)*IMGSZ + (size_t)gy*PSZ + py)*IMGSZ + gx*PSZ + px];
}

// ---------------- FFMA2 SGEMM (fp32 path) -----------------------------------
// BIT-EXACT k-ascending fma.rn.f32x2 chain per element; frozen epilogue order.
// K-tile 16, A staged as duplicated (a,a) pairs.
// mode 0: plain; 1: +residual; 2: tanh-GELU
#define SMEM_F32 49152   // [2][16][256] As2 (32KB) + [2][16][128] Bs (16KB)

__global__ void __launch_bounds__(256, 2)
gemm128_kernel(const float* __restrict__ A, const float* __restrict__ Bm,
               const float* __restrict__ bias, const float* __restrict__ res,
               float* __restrict__ C, int M, int N, int K, int mode)
{
    extern __shared__ float smf[];
    float* As2 = smf;                 // [2][16][256]
    float* Bs  = smf + 2*16*256;      // [2][16][128]
    int tid = threadIdx.x;
    int tx = tid & 15, ty = tid >> 4;
    int m0 = blockIdx.y * 128, n0 = blockIdx.x * 128;
    int ar = tid >> 1, ak8 = (tid & 1) * 8;   // A: row, k-offset (8 floats)
    int br8 = tid >> 5, bc = (tid & 31) * 4;  // B: k-row base, col offset
    bool avalid = (m0 + ar) < M;
    bool bvalid = (n0 + bc) < N;
    const float* Aptr = A + (size_t)(m0 + ar) * K + ak8;
    const float* Bptr = Bm + (size_t)br8 * N + n0 + bc;
    const float4 z4 = make_float4(0.f,0.f,0.f,0.f);
    int T = K >> 4;

    float4 av0 = avalid ? *(const float4*)Aptr        : z4;
    float4 av1 = avalid ? *(const float4*)(Aptr + 4)  : z4;
    float4 bv0 = bvalid ? *(const float4*)Bptr                 : z4;
    float4 bv1 = bvalid ? *(const float4*)(Bptr + (size_t)8*N) : z4;
    {
        float va[8] = {av0.x,av0.y,av0.z,av0.w,av1.x,av1.y,av1.z,av1.w};
        #pragma unroll
        for (int q = 0; q < 8; q++)
            *(float2*)&As2[(0*16 + ak8 + q)*256 + 2*ar] = make_float2(va[q], va[q]);
        *(float4*)&Bs[(0*16 + br8)*128 + bc]     = bv0;
        *(float4*)&Bs[(0*16 + br8 + 8)*128 + bc] = bv1;
    }
    __syncthreads();

    unsigned long long acc2[8][4];
    #pragma unroll
    for (int i = 0; i < 8; i++)
        #pragma unroll
        for (int j = 0; j < 4; j++) acc2[i][j] = 0ull;

    for (int t = 0; t < T; t++) {
        int cur = t & 1;
        if (t + 1 < T) {
            const float* Ap = Aptr + (size_t)(t+1)*16;
            const float* Bp = Bptr + (size_t)(t+1)*16*N;
            av0 = avalid ? *(const float4*)Ap       : z4;
            av1 = avalid ? *(const float4*)(Ap + 4) : z4;
            bv0 = bvalid ? *(const float4*)Bp                 : z4;
            bv1 = bvalid ? *(const float4*)(Bp + (size_t)8*N) : z4;
        }
        #pragma unroll
        for (int kk = 0; kk < 16; kk++) {
            const ulonglong2* pa = (const ulonglong2*)&As2[(cur*16 + kk)*256 + ty*16];
            ulonglong2 p0 = pa[0], p1 = pa[1], p2 = pa[2], p3 = pa[3];
            unsigned long long a2[8] = {p0.x, p0.y, p1.x, p1.y, p2.x, p2.y, p3.x, p3.y};
            const ulonglong2* pb = (const ulonglong2*)&Bs[(cur*16 + kk)*128 + tx*8];
            ulonglong2 q0 = pb[0], q1 = pb[1];
            unsigned long long b2[4] = {q0.x, q0.y, q1.x, q1.y};
            #pragma unroll
            for (int i = 0; i < 8; i++)
                #pragma unroll
                for (int j = 0; j < 4; j++)
                    asm("fma.rn.f32x2 %0, %1, %2, %0;"
                        : "+l"(acc2[i][j]) : "l"(a2[i]), "l"(b2[j]));
        }
        if (t + 1 < T) {
            int nxt = cur ^ 1;
            float va[8] = {av0.x,av0.y,av0.z,av0.w,av1.x,av1.y,av1.z,av1.w};
            #pragma unroll
            for (int q = 0; q < 8; q++)
                *(float2*)&As2[(nxt*16 + ak8 + q)*256 + 2*ar] = make_float2(va[q], va[q]);
            *(float4*)&Bs[(nxt*16 + br8)*128 + bc]     = bv0;
            *(float4*)&Bs[(nxt*16 + br8 + 8)*128 + bc] = bv1;
            __syncthreads();
        }
    }
    #pragma unroll
    for (int i = 0; i < 8; i++) {
        int m = m0 + ty*8 + i;
        if (m >= M) continue;
        float c[8];
        #pragma unroll
        for (int j = 0; j < 4; j++)
            asm("mov.b64 {%0, %1}, %2;" : "=f"(c[2*j]), "=f"(c[2*j+1]) : "l"(acc2[i][j]));
        #pragma unroll
        for (int j = 0; j < 8; j++) {
            int n = n0 + tx*8 + j;
            if (n >= N) continue;
            float v = c[j] + bias[n];
            if (mode == 1) {
                v += res[(size_t)m*N + n];
            } else if (mode == 2) {
                float x = v;
                v = 0.5f * x * (1.0f + tanhf(0.7978845608028654f * (x + 0.044715f*x*x*x)));
            }
            C[(size_t)m*N + n] = v;
        }
    }
}

// ---------------- mma.sync bf16 2-split/3-product GEMM (layers > SELL) ------
// 3-stage cp.async pipeline: two K-tiles always in flight (wait_group 2).
#define APITCH   144
#define SPLIT_SZ (128*APITCH)          // 18432
#define STG_SZ   (4*SPLIT_SZ)          // 73728
#define NSTAGE   3
#define SMEM_MMA (NSTAGE*STG_SZ)       // 221184

__global__ void __launch_bounds__(512, 1)
gemm_mma(const bf16* __restrict__ Ah, const bf16* __restrict__ Am,
         const bf16* __restrict__ Bh, const bf16* __restrict__ Bm,
         const float* __restrict__ bias, const float* __restrict__ res,
         float* __restrict__ Cf, bf16* __restrict__ Ch, bf16* __restrict__ Cm,
         int M, int N, int K, int mode)
{
    extern __shared__ char smem[];
    uint32_t sb = smem_u32(smem);
    int tid = threadIdx.x, lane = tid & 31, warp = tid >> 5;
    int wm = warp >> 2, wn = warp & 3;         // 4 x 4 warps, 32x32 tile each
    int m0 = blockIdx.y * 128, n0 = blockIdx.x * 128;

    float acc[2][4][4] = {};
    int lr = lane & 15;
    int lk = (lane >> 4) * 16;
    int T = K >> 6;                            // K/64 tiles

    auto issue_stage = [&](int buf, int kc) {
        uint32_t base = sb + buf * STG_SZ;
        #pragma unroll
        for (int j = 0; j < 2; j++) {
            int u = j * 512 + tid;
            int row = u >> 3, q = u & 7;       // 128 rows x 8 quads(16B)
            uint32_t d = base + row*APITCH + q*16;
            size_t goff = (size_t)row * K + kc + q*8;
            int asz = (m0 + row < M) ? 16 : 0;
            cpasync16(d + 0*SPLIT_SZ, Ah + (size_t)m0*K + goff, asz);
            cpasync16(d + 1*SPLIT_SZ, Am + (size_t)m0*K + goff, asz);
            cpasync16(d + 2*SPLIT_SZ, Bh + (size_t)n0*K + goff, 16);
            cpasync16(d + 3*SPLIT_SZ, Bm + (size_t)n0*K + goff, 16);
        }
    };

    // prologue: stages 0 and 1 in flight
    issue_stage(0, 0);
    CP_COMMIT();
    if (T > 1) issue_stage(1, 64);
    CP_COMMIT();

    int buf = 0;
    for (int t = 0; t < T; t++) {
        if (t + 2 < T) {
            int nb = buf + 2; if (nb >= NSTAGE) nb -= NSTAGE;
            issue_stage(nb, (t + 2) * 64);
        }
        CP_COMMIT();
        CP_WAIT2();                             // stage t complete (<=2 pending)
        __syncthreads();

        uint32_t stg = sb + buf * STG_SZ;
        #pragma unroll
        for (int kh = 0; kh < 4; kh++) {
            int kb = kh * 32 + lk;
            uint32_t afr[2][2][4], bfr[2][4][2];
            #pragma unroll
            for (int s = 0; s < 2; s++) {
                #pragma unroll
                for (int mt = 0; mt < 2; mt++) {
                    uint32_t ad = stg + s*SPLIT_SZ + (uint32_t)(wm*32 + mt*16 + lr)*APITCH + kb;
                    LDSM4(afr[s][mt][0], afr[s][mt][1], afr[s][mt][2], afr[s][mt][3], ad);
                }
                #pragma unroll
                for (int np = 0; np < 2; np++) {
                    uint32_t r0, r1, r2, r3;
                    uint32_t bd = stg + (2+s)*SPLIT_SZ + (uint32_t)(wn*32 + np*16 + lr)*APITCH + kb;
                    LDSM4(r0, r1, r2, r3, bd);
                    bfr[s][np*2+0][0] = r0; bfr[s][np*2+0][1] = r2;
                    bfr[s][np*2+1][0] = r1; bfr[s][np*2+1][1] = r3;
                }
            }
            // products: hh, hm, mh
            #pragma unroll
            for (int p = 0; p < 3; p++) {
                int sa = (p == 2) ? 1 : 0;
                int sbp = (p == 1) ? 1 : 0;
                #pragma unroll
                for (int mt = 0; mt < 2; mt++)
                    #pragma unroll
                    for (int nt = 0; nt < 4; nt++)
                        MMA16816(acc[mt][nt], afr[sa][mt], bfr[sbp][nt]);
            }
        }
        __syncthreads();
        buf++; if (buf >= NSTAGE) buf = 0;
    }

    // ---- epilogue
    #pragma unroll
    for (int mt = 0; mt < 2; mt++) {
        #pragma unroll
        for (int h2 = 0; h2 < 2; h2++) {
            int rr = m0 + wm*32 + mt*16 + (lane >> 2) + h2*8;
            if (rr >= M) continue;
            #pragma unroll
            for (int nt = 0; nt < 4; nt++) {
                int c = n0 + wn*32 + nt*8 + (lane & 3)*2;
                float v0 = acc[mt][nt][h2*2+0] + bias[c];
                float v1 = acc[mt][nt][h2*2+1] + bias[c+1];
                size_t o = (size_t)rr * N + c;
                if (mode == 1) { v0 += res[o]; v1 += res[o+1]; }
                if (mode <= 1) {
                    float2 v; v.x = v0; v.y = v1;
                    *(float2*)&Cf[o] = v;
                } else {
                    float g0 = 0.5f*v0*(1.0f + tanhf(0.7978845608028654f*(v0 + 0.044715f*v0*v0*v0)));
                    float g1 = 0.5f*v1*(1.0f + tanhf(0.7978845608028654f*(v1 + 0.044715f*v1*v1*v1)));
                    bf16 h0, m0b, h1, m1b;
                    split2(g0, h0, m0b);
                    split2(g1, h1, m1b);
                    *(__nv_bfloat162*)&Ch[o] = __nv_bfloat162(h0, h1);
                    *(__nv_bfloat162*)&Cm[o] = __nv_bfloat162(m0b, m1b);
                }
            }
        }
    }
}

// ---------------- layernorm: fp32 out and/or split2 out ---------------------
__global__ void ln_kernel(const float* __restrict__ X, const float* __restrict__ g,
                          const float* __restrict__ b, float* __restrict__ Yf,
                          bf16* __restrict__ Yh, bf16* __restrict__ Ym)
{
    int row = blockIdx.x;
    const float* x = X + (size_t)row * DIM;
    __shared__ float red[256];
    int tid = threadIdx.x;
    float v0 = x[tid], v1 = x[tid+256], v2 = x[tid+512];
    red[tid] = v0 + v1 + v2;
    __syncthreads();
    for (int o = 128; o > 0; o >>= 1) { if (tid < o) red[tid] += red[tid+o]; __syncthreads(); }
    float mean = red[0] * (1.0f / DIM);
    __syncthreads();
    float d0 = v0-mean, d1 = v1-mean, d2 = v2-mean;
    red[tid] = d0*d0 + d1*d1 + d2*d2;
    __syncthreads();
    for (int o = 128; o > 0; o >>= 1) { if (tid < o) red[tid] += red[tid+o]; __syncthreads(); }
    float rstd = 1.0f / sqrtf(red[0] * (1.0f / DIM) + LNEPS);
    size_t base = (size_t)row * DIM;
    float o0 = d0*rstd*g[tid]     + b[tid];
    float o1 = d1*rstd*g[tid+256] + b[tid+256];
    float o2 = d2*rstd*g[tid+512] + b[tid+512];
    if (Yf) { Yf[base+tid] = o0; Yf[base+tid+256] = o1; Yf[base+tid+512] = o2; }
    if (Yh) {
        bf16 h, m;
        split2(o0, h, m); Yh[base+tid]     = h; Ym[base+tid]     = m;
        split2(o1, h, m); Yh[base+tid+256] = h; Ym[base+tid+256] = m;
        split2(o2, h, m); Yh[base+tid+512] = h; Ym[base+tid+512] = m;
    }
}

// ---------------- assemble X = [cls | patches] + pos ------------------------
__global__ void assemble_kernel(const float* __restrict__ PE, const float* __restrict__ cls,
                                const float* __restrict__ pos, float* __restrict__ X)
{
    size_t idx = (size_t)blockIdx.x * 256 + threadIdx.x;
    const size_t total = (size_t)BATCH * LFULL * DIM;
    if (idx >= total) return;
    int d = (int)(idx % DIM);
    int r = (int)((idx / DIM) % LFULL);
    int b = (int)(idx / ((size_t)LFULL * DIM));
    float v = (r == 0) ? cls[d] : PE[((size_t)b*NPATCH + (r-1))*DIM + d];
    X[idx] = v + pos[(size_t)r*DIM + d];
}

// ---------------- tiled attention v3: register microtiles, LDS-lean ---------
#define QT 32
#define KC 32
__global__ void __launch_bounds__(256)
attn3_kernel(const float* __restrict__ QKV, float* __restrict__ Of,
             bf16* __restrict__ Oh, bf16* __restrict__ Om, int L)
{
    int q0b = blockIdx.x * QT;
    int h  = blockIdx.y;
    int b  = blockIdx.z;
    __shared__ float Qt[DH][34];                 // Q transposed [d][q]
    __shared__ __align__(16) float KVu[64*36];   // union: Kt[d][kk] pitch 36 / Vs[kk][d] pitch 68
    __shared__ float sc[QT][224];
    int tid = threadIdx.x;
    const size_t rs = 3 * DIM;
    const float* base = QKV + (size_t)b * L * rs;

    // load Q transposed
    for (int i = tid; i < QT*DH; i += 256) {
        int qq = i >> 6, d = i & 63;
        Qt[d][qq] = (q0b + qq < L) ? base[(size_t)(q0b+qq)*rs + h*DH + d] : 0.f;
    }

    int ty = tid >> 4, tx = tid & 15;            // score: 2q x 2k ; V: 2q x 4d
    // ---- score pass
    for (int kc = 0; kc < L; kc += KC) {
        __syncthreads();
        for (int i = tid; i < KC*DH; i += 256) {
            int kk = i >> 6, d = i & 63;
            KVu[d*36 + kk] = (kc + kk < L) ? base[(size_t)(kc+kk)*rs + DIM + h*DH + d] : 0.f;
        }
        __syncthreads();
        float a00 = 0.f, a01 = 0.f, a10 = 0.f, a11 = 0.f;
        #pragma unroll 8
        for (int d = 0; d < DH; d++) {
            float2 qv = *(const float2*)&Qt[d][2*ty];
            float k0 = KVu[d*36 + 2*tx];
            float k1 = KVu[d*36 + 2*tx + 1];
            a00 += qv.x * k0; a01 += qv.x * k1;
            a10 += qv.y * k0; a11 += qv.y * k1;
        }
        int k0i = kc + 2*tx, k1i = k0i + 1;
        sc[2*ty+0][k0i] = (k0i < L) ? a00 * 0.125f : -1e30f;
        sc[2*ty+0][k1i] = (k1i < L) ? a01 * 0.125f : -1e30f;
        sc[2*ty+1][k0i] = (k0i < L) ? a10 * 0.125f : -1e30f;
        sc[2*ty+1][k1i] = (k1i < L) ? a11 * 0.125f : -1e30f;
    }
    __syncthreads();
    // ---- softmax (identical code to previous rounds)
    int wid = tid >> 5, lane = tid & 31;
    for (int qq = wid; qq < QT; qq += 8) {
        float mx = -1e30f;
        for (int k = lane; k < L; k += 32) mx = fmaxf(mx, sc[qq][k]);
        for (int o = 16; o; o >>= 1) mx = fmaxf(mx, __shfl_xor_sync(~0u, mx, o));
        float sum = 0.f;
        for (int k = lane; k < L; k += 32) { float e = expf(sc[qq][k] - mx); sc[qq][k] = e; sum += e; }
        for (int o = 16; o; o >>= 1) sum += __shfl_xor_sync(~0u, sum, o);
        float inv = 1.0f / sum;
        for (int k = lane; k < L; k += 32) sc[qq][k] *= inv;
    }
    // ---- V pass: thread owns rows (2*ty, 2*ty+1) x cols (4*tx .. 4*tx+3)
    float ov0[4] = {}, ov1[4] = {};
    int d0 = 4 * tx;
    for (int kc = 0; kc < L; kc += KC) {
        __syncthreads();
        for (int i = tid; i < KC*DH; i += 256) {
            int kk = i >> 6, dd = i & 63;
            KVu[kk*68 + dd] = (kc + kk < L) ? base[(size_t)(kc+kk)*rs + 2*DIM + h*DH + dd] : 0.f;
        }
        __syncthreads();
        int kmax = min(KC, L - kc);
        for (int kk = 0; kk < kmax; kk++) {
            float s0 = sc[2*ty+0][kc+kk];
            float s1 = sc[2*ty+1][kc+kk];
            float4 v = *(const float4*)&KVu[kk*68 + d0];
            ov0[0] += s0 * v.x; ov0[1] += s0 * v.y; ov0[2] += s0 * v.z; ov0[3] += s0 * v.w;
            ov1[0] += s1 * v.x; ov1[1] += s1 * v.y; ov1[2] += s1 * v.z; ov1[3] += s1 * v.w;
        }
    }
    #pragma unroll
    for (int i = 0; i < 2; i++) {
        int q = q0b + 2*ty + i;
        if (q >= L) continue;
        const float* src = (i == 0) ? ov0 : ov1;
        size_t o = ((size_t)(b*L + q))*DIM + h*DH + d0;
        if (Of) {
            *(float4*)&Of[o] = make_float4(src[0], src[1], src[2], src[3]);
        } else {
            bf16 h0, m0v, h1, m1v;
            #pragma unroll
            for (int j = 0; j < 4; j += 2) {
                split2(src[j],   h0, m0v);
                split2(src[j+1], h1, m1v);
                *(__nv_bfloat162*)&Oh[o + j] = __nv_bfloat162(h0, h1);
                *(__nv_bfloat162*)&Om[o + j] = __nv_bfloat162(m0v, m1v);
            }
        }
    }
}

// ---------------- cosine similarity (fp64) ----------------------------------
__global__ void sim_kernel(const float* __restrict__ X, float* __restrict__ SIM)
{
    int p = blockIdx.x, b = blockIdx.y;
    const float* cls = X + (size_t)b * LFULL * DIM;
    const float* pt  = X + ((size_t)b*LFULL + 1 + p) * DIM;
    int tid = threadIdx.x;
    double dot = 0.0, nc = 0.0, np = 0.0;
    for (int d = tid; d < DIM; d += 128) {
        double c = (double)cls[d], v = (double)pt[d];
        dot += c*v; nc += c*c; np += v*v;
    }
    __shared__ double r1[128], r2[128], r3[128];
    r1[tid] = dot; r2[tid] = nc; r3[tid] = np;
    __syncthreads();
    for (int o = 64; o > 0; o >>= 1) {
        if (tid < o) { r1[tid]+=r1[tid+o]; r2[tid]+=r2[tid+o]; r3[tid]+=r3[tid+o]; }
        __syncthreads();
    }
    if (tid == 0) {
        double den = sqrt(r2[0]) * sqrt(r3[0]);
        den = den > 1e-8 ? den : 1e-8;
        SIM[b*NPATCH + p] = (float)(r1[0] / den);
    }
}

// ---------------- stable top-K ----------------------------------------------
__global__ void topk_kernel(const float* __restrict__ SIM, int* __restrict__ IDX)
{
    int b = blockIdx.x;
    __shared__ float s[NPATCH];
    int tid = threadIdx.x;
    if (tid < NPATCH) s[tid] = SIM[b*NPATCH + tid];
    __syncthreads();
    if (tid < NPATCH) {
        float si = s[tid];
        int rank = 0;
        for (int j = 0; j < NPATCH; j++) {
            float sj = s[j];
            rank += (sj > si) || (sj == si && j < tid);
        }
        if (rank < KEEP) IDX[b*KEEP + rank] = tid;
    }
}

// ---------------- gather ----------------------------------------------------
__global__ void gather_kernel(const float* __restrict__ X, const int* __restrict__ IDX,
                              float* __restrict__ X2)
{
    size_t idx = (size_t)blockIdx.x * 256 + threadIdx.x;
    const size_t total = (size_t)BATCH * LPRUNE * DIM;
    if (idx >= total) return;
    int d = (int)(idx % DIM);
    int r = (int)((idx / DIM) % LPRUNE);
    int b = (int)(idx / ((size_t)LPRUNE * DIM));
    int src = (r == 0) ? 0 : (1 + IDX[b*KEEP + (r-1)]);
    X2[idx] = X[((size_t)b*LFULL + src)*DIM + d];
}

// ---------------- host orchestration ----------------------------------------
extern "C" void kernel_launch(void* const* d_in, const int* in_sizes, int n_in,
                              void* d_out, int out_size)
{
    const float* inputs    = (const float*)d_in[0];
    const float* patch_w   = (const float*)d_in[1];
    const float* patch_b   = (const float*)d_in[2];
    const float* cls_token = (const float*)d_in[3];
    const float* pos_embed = (const float*)d_in[4];
    const float* qkv_w     = (const float*)d_in[5];
    const float* qkv_b     = (const float*)d_in[6];
    const float* proj_w    = (const float*)d_in[7];
    const float* proj_b    = (const float*)d_in[8];
    const float* ln1_g     = (const float*)d_in[9];
    const float* ln1_b     = (const float*)d_in[10];
    const float* ln2_g     = (const float*)d_in[11];
    const float* ln2_b     = (const float*)d_in[12];
    const float* mlp_w1    = (const float*)d_in[13];
    const float* mlp_b1    = (const float*)d_in[14];
    const float* mlp_w2    = (const float*)d_in[15];
    const float* mlp_b2    = (const float*)d_in[16];
    const float* norm_g    = (const float*)d_in[17];
    const float* norm_b    = (const float*)d_in[18];
    const float* head_w    = (const float*)d_in[19];
    const float* head_b    = (const float*)d_in[20];

    float *X, *X2, *Hf, *QKV, *Ofp, *M1f, *PT, *PE, *SIM; int* IDX;
    bf16 *AH, *AM, *OH, *OM, *M1H, *M1M, *WH, *WM;
    cudaGetSymbolAddress((void**)&X,   g_X);
    cudaGetSymbolAddress((void**)&X2,  g_X2);
    cudaGetSymbolAddress((void**)&Hf,  g_Hf);
    cudaGetSymbolAddress((void**)&QKV, g_QKV);
    cudaGetSymbolAddress((void**)&Ofp, g_O);
    cudaGetSymbolAddress((void**)&M1f, g_M1);
    cudaGetSymbolAddress((void**)&PT,  g_PT);
    cudaGetSymbolAddress((void**)&PE,  g_PE);
    cudaGetSymbolAddress((void**)&SIM, g_SIM);
    cudaGetSymbolAddress((void**)&IDX, g_IDX);
    cudaGetSymbolAddress((void**)&AH,  g_AH);  cudaGetSymbolAddress((void**)&AM, g_AM);
    cudaGetSymbolAddress((void**)&OH,  g_OH);  cudaGetSymbolAddress((void**)&OM, g_OM);
    cudaGetSymbolAddress((void**)&M1H, g_M1H); cudaGetSymbolAddress((void**)&M1M, g_M1M);
    cudaGetSymbolAddress((void**)&WH,  g_WH);  cudaGetSymbolAddress((void**)&WM, g_WM);

    cudaFuncSetAttribute(gemm_mma, cudaFuncAttributeMaxDynamicSharedMemorySize, SMEM_MMA);
    cudaFuncSetAttribute(gemm128_kernel, cudaFuncAttributeMaxDynamicSharedMemorySize, SMEM_F32);

    // ---- weight prep for mma layers (transpose + split2)
    {
        dim3 blk(32, 8);
        wsplit_kernel<<<dim3(24, 72, 12), blk>>>(qkv_w,  WH+OFF_QKV,  WM+OFF_QKV,  768, 2304);
        wsplit_kernel<<<dim3(24, 24, 12), blk>>>(proj_w, WH+OFF_PROJ, WM+OFF_PROJ, 768, 768);
        wsplit_kernel<<<dim3(24, 96, 12), blk>>>(mlp_w1, WH+OFF_W1,   WM+OFF_W1,   768, 3072);
        wsplit_kernel<<<dim3(96, 24, 12), blk>>>(mlp_w2, WH+OFF_W2,   WM+OFF_W2,   3072, 768);
    }

    // ---- patch embedding (fp32 FFMA2 path — bit-exact chain)
    {
        size_t total = (size_t)BATCH * NPATCH * DIM;
        im2col_kernel<<<(unsigned)((total + 255)/256), 256>>>(inputs, PT);
        dim3 g(6, 49);
        gemm128_kernel<<<g, 256, SMEM_F32>>>(PT, patch_w, patch_b, nullptr, PE,
                                             BATCH*NPATCH, DIM, DIM, 0);
        size_t tot2 = (size_t)BATCH * LFULL * DIM;
        assemble_kernel<<<(unsigned)((tot2 + 255)/256), 256>>>(PE, cls_token, pos_embed, X);
    }

    float* cur = X;
    int L = LFULL;
    for (int n = 0; n < NLAYER; n++) {
        int M = BATCH * L;
        int Mt = (M + 127) / 128;
        if (n <= SELL) {
            // ======== fp32 FFMA2 path (bit-exact frozen numerics; selection-safe)
            ln_kernel<<<M, 256>>>(cur, ln1_g + (size_t)n*DIM, ln1_b + (size_t)n*DIM,
                                  Hf, nullptr, nullptr);
            gemm128_kernel<<<dim3(18, Mt), 256, SMEM_F32>>>(Hf, qkv_w + (size_t)n*DIM*3*DIM,
                qkv_b + (size_t)n*3*DIM, nullptr, QKV, M, 3*DIM, DIM, 0);
            {
                dim3 g((L + QT - 1)/QT, NHEAD, BATCH);
                attn3_kernel<<<g, 256>>>(QKV, Ofp, nullptr, nullptr, L);
            }
            gemm128_kernel<<<dim3(6, Mt), 256, SMEM_F32>>>(Ofp, proj_w + (size_t)n*DIM*DIM,
                proj_b + (size_t)n*DIM, cur, cur, M, DIM, DIM, 1);
            ln_kernel<<<M, 256>>>(cur, ln2_g + (size_t)n*DIM, ln2_b + (size_t)n*DIM,
                                  Hf, nullptr, nullptr);
            gemm128_kernel<<<dim3(24, Mt), 256, SMEM_F32>>>(Hf, mlp_w1 + (size_t)n*DIM*DFFN,
                mlp_b1 + (size_t)n*DFFN, nullptr, M1f, M, DFFN, DIM, 2);
            gemm128_kernel<<<dim3(6, Mt), 256, SMEM_F32>>>(M1f, mlp_w2 + (size_t)n*DFFN*DIM,
                mlp_b2 + (size_t)n*DIM, cur, cur, M, DIM, DFFN, 1);
            if (n == SELL) {
                dim3 gs(NPATCH, BATCH);
                sim_kernel<<<gs, 128>>>(cur, SIM);
                topk_kernel<<<BATCH, 256>>>(SIM, IDX);
                size_t tot = (size_t)BATCH * LPRUNE * DIM;
                gather_kernel<<<(unsigned)((tot + 255)/256), 256>>>(cur, IDX, X2);
                cur = X2;
                L = LPRUNE;
            }
        } else {
            // ======== bf16 mma path (post-selection)
            ln_kernel<<<M, 256>>>(cur, ln1_g + (size_t)n*DIM, ln1_b + (size_t)n*DIM,
                                  nullptr, AH, AM);
            gemm_mma<<<dim3(18, Mt), 512, SMEM_MMA>>>(AH, AM,
                WH+OFF_QKV + (size_t)n*2304*768, WM+OFF_QKV + (size_t)n*2304*768,
                qkv_b + (size_t)n*3*DIM, nullptr, QKV, nullptr, nullptr, M, 3*DIM, DIM, 0);
            {
                dim3 g((L + QT - 1)/QT, NHEAD, BATCH);
                attn3_kernel<<<g, 256>>>(QKV, nullptr, OH, OM, L);
            }
            gemm_mma<<<dim3(6, Mt), 512, SMEM_MMA>>>(OH, OM,
                WH+OFF_PROJ + (size_t)n*768*768, WM+OFF_PROJ + (size_t)n*768*768,
                proj_b + (size_t)n*DIM, cur, cur, nullptr, nullptr, M, DIM, DIM, 1);
            ln_kernel<<<M, 256>>>(cur, ln2_g + (size_t)n*DIM, ln2_b + (size_t)n*DIM,
                                  nullptr, AH, AM);
            gemm_mma<<<dim3(24, Mt), 512, SMEM_MMA>>>(AH, AM,
                WH+OFF_W1 + (size_t)n*3072*768, WM+OFF_W1 + (size_t)n*3072*768,
                mlp_b1 + (size_t)n*DFFN, nullptr, nullptr, M1H, M1M, M, DFFN, DIM, 2);
            gemm_mma<<<dim3(6, Mt), 512, SMEM_MMA>>>(M1H, M1M,
                WH+OFF_W2 + (size_t)n*768*3072, WM+OFF_W2 + (size_t)n*768*3072,
                mlp_b2 + (size_t)n*DIM, cur, cur, nullptr, nullptr, M, DIM, DFFN, 1);
        }
    }

    // ---- final LN + head (fp32 FFMA2 path)
    {
        int M = BATCH * LPRUNE;
        ln_kernel<<<M, 256>>>(cur, norm_g, norm_b, Hf, nullptr, nullptr);
        dim3 g(1, (M + 127)/128);
        gemm128_kernel<<<g, 256, SMEM_F32>>>(Hf, head_w, head_b, nullptr, (float*)d_out,
                                             M, NCLS, DIM, 0);
    }
}